// round 8
// baseline (speedup 1.0000x reference)
#include <cuda_runtime.h>
#include <cuda_fp16.h>
#include <cstdint>

// ---------------------------------------------------------------------------
// MultiHeadAttn: T=2048, B=4, N_HEAD=16, D_HEAD=64, D_MODEL=1024
// Round 7: 512-thread CTAs (1 CTA owns full SM: 16 warps resident vs 8).
// GEMM BM=128,BN=256, 3-stage cp.async ring. Flash: 256 q-rows/CTA sharing
// K/V tiles. Same per-warp mma structure as R6.
// ---------------------------------------------------------------------------

#define T_LEN 2048
#define BATCH 4
#define NHEAD 16
#define DHEAD 64
#define DMODEL 1024
#define MROWS (T_LEN * BATCH)        // 8192
#define QSCALE_LOG2E 0.180336878f    // (1/sqrt(64)) * log2(e)
#define MASKF -1e38f

__device__ __half g_hh[MROWS * DMODEL];
__device__ __half g_wqkvh[3072 * DMODEL];
__device__ __half g_woh[DMODEL * DMODEL];
__device__ float  g_mskf[BATCH * T_LEN];                // 0 or -1e38, [b][t]
__device__ __half g_Q[BATCH * NHEAD * T_LEN * DHEAD];   // [bh][t][d]
__device__ __half g_K[BATCH * NHEAD * T_LEN * DHEAD];
__device__ __half g_V[BATCH * NHEAD * T_LEN * DHEAD];
__device__ __half g_att[MROWS * DMODEL];
__device__ float  g_res[MROWS * DMODEL];

#define NEG_INF __int_as_float(0xff800000)

__device__ __forceinline__ float clamp_m(float x) { return fmaxf(x, -1e30f); }

__device__ __forceinline__ float ex2(float x) {
    float r;
    asm("ex2.approx.ftz.f32 %0, %1;" : "=f"(r) : "f"(x));
    return r;
}

__device__ __forceinline__ void mma_f16(float& c0, float& c1, float& c2, float& c3,
                                        unsigned a0, unsigned a1, unsigned a2, unsigned a3,
                                        unsigned b0, unsigned b1) {
    asm volatile(
        "mma.sync.aligned.m16n8k16.row.col.f32.f16.f16.f32 "
        "{%0,%1,%2,%3},{%4,%5,%6,%7},{%8,%9},{%0,%1,%2,%3};"
        : "+f"(c0), "+f"(c1), "+f"(c2), "+f"(c3)
        : "r"(a0), "r"(a1), "r"(a2), "r"(a3), "r"(b0), "r"(b1));
}

__device__ __forceinline__ void ldsm_x4(unsigned& r0, unsigned& r1,
                                        unsigned& r2, unsigned& r3,
                                        const __half* p) {
    unsigned sa = (unsigned)__cvta_generic_to_shared(p);
    asm volatile("ldmatrix.sync.aligned.m8n8.x4.shared.b16 {%0,%1,%2,%3}, [%4];"
                 : "=r"(r0), "=r"(r1), "=r"(r2), "=r"(r3) : "r"(sa));
}

__device__ __forceinline__ void ldsm_x4_trans(unsigned& r0, unsigned& r1,
                                              unsigned& r2, unsigned& r3,
                                              const __half* p) {
    unsigned sa = (unsigned)__cvta_generic_to_shared(p);
    asm volatile("ldmatrix.sync.aligned.m8n8.x4.trans.shared.b16 {%0,%1,%2,%3}, [%4];"
                 : "=r"(r0), "=r"(r1), "=r"(r2), "=r"(r3) : "r"(sa));
}

__device__ __forceinline__ unsigned pack_h2(float a, float b) {
    __half2 h = __floats2half2_rn(a, b);
    return *(unsigned*)&h;
}

__device__ __forceinline__ void cp16(const void* smem_dst, const void* gsrc) {
    unsigned sa = (unsigned)__cvta_generic_to_shared(smem_dst);
    unsigned long long ga = (unsigned long long)__cvta_generic_to_global(gsrc);
    asm volatile("cp.async.cg.shared.global [%0], [%1], 16;" :: "r"(sa), "l"(ga));
}
__device__ __forceinline__ void cp_commit() { asm volatile("cp.async.commit_group;"); }
template <int N>
__device__ __forceinline__ void cp_wait() { asm volatile("cp.async.wait_group %0;" :: "n"(N)); }

// ---------------------------------------------------------------------------
// Kernel 0: fused dtype converts + mask->float pack
// ---------------------------------------------------------------------------
#define H4   (MROWS * DMODEL / 4)
#define WQ4  (1024 * DMODEL / 4)
#define WKV4 (2048 * DMODEL / 4)
#define WO4  (DMODEL * DMODEL / 4)
#define TOT4 (H4 + WQ4 + WKV4 + WO4)

__global__ __launch_bounds__(256) void conv_all_kernel(
    const float* __restrict__ h, const float* __restrict__ wq,
    const float* __restrict__ wkv, const float* __restrict__ wo,
    const int* __restrict__ mask)
{
    int i = blockIdx.x * 256 + threadIdx.x;
    if (i < TOT4) {
        const float* src;
        __half* dst;
        int off;
        if (i < H4) { src = h; dst = g_hh; off = i; }
        else if (i < H4 + WQ4) { src = wq; dst = g_wqkvh; off = i - H4; }
        else if (i < H4 + WQ4 + WKV4) { src = wkv; dst = g_wqkvh + 1024 * DMODEL; off = i - H4 - WQ4; }
        else { src = wo; dst = g_woh; off = i - H4 - WQ4 - WKV4; }
        float4 v = ((const float4*)src)[off];
        uint2 u = {pack_h2(v.x, v.y), pack_h2(v.z, v.w)};
        ((uint2*)dst)[off] = u;
    } else {
        int t = i - TOT4;
        if (t < T_LEN) {
#pragma unroll
            for (int b = 0; b < BATCH; b++)
                g_mskf[b * T_LEN + t] = (mask[t * BATCH + b] != 0) ? MASKF : 0.f;
        }
    }
}

// ---------------------------------------------------------------------------
// fp16 GEMM: BM=128, BN=256, BK=64; 512 threads (16 warps, 4x4), warp tile
// 32x64; 3-stage cp.async ring. 1 CTA/SM, full RF.
// ---------------------------------------------------------------------------
#define BK 64
#define HSTR 72
#define GEMM_A_HALFS (128 * HSTR)               // 9216
#define GEMM_STAGE_HALFS ((128 + 256) * HSTR)   // 27648
#define GEMM_SMEM_BYTES (3 * GEMM_STAGE_HALFS * 2)   // 165888

__device__ __forceinline__ void gemm_load_stage(__half* stage,
                                                const __half* Ag, const __half* Bg,
                                                int tid) {
    __half* As = stage;
    __half* Bs = stage + GEMM_A_HALFS;
#pragma unroll
    for (int i = 0; i < 2; i++) {                 // A: 1024 chunks
        int s = tid + i * 512;
        int r = s >> 3, c8 = (s & 7) << 3;
        cp16(As + r * HSTR + c8, Ag + (size_t)r * DMODEL + c8);
    }
#pragma unroll
    for (int i = 0; i < 4; i++) {                 // B: 2048 chunks
        int s = tid + i * 512;
        int r = s >> 3, c8 = (s & 7) << 3;
        cp16(Bs + r * HSTR + c8, Bg + (size_t)r * DMODEL + c8);
    }
}

__device__ __forceinline__ void gemm_mainloop(__half* smem, const __half* Ag,
                                              const __half* Bg, float acc[2][8][4],
                                              int tid) {
    const int warp = tid >> 5, lane = tid & 31;
    const int wr = warp >> 2, wc = warp & 3;
    const int lrow = lane & 15, lcol = (lane >> 4) << 3;

    gemm_load_stage(smem, Ag, Bg, tid);
    cp_commit();
    gemm_load_stage(smem + GEMM_STAGE_HALFS, Ag + BK, Bg + BK, tid);
    cp_commit();

    for (int kt = 0; kt < 16; kt++) {
        if (kt == 15) { cp_wait<0>(); } else { cp_wait<1>(); }
        __syncthreads();

        const __half* stage = smem + (kt % 3) * GEMM_STAGE_HALFS;
        const __half (*As)[HSTR] = (const __half (*)[HSTR])stage;
        const __half (*Bs)[HSTR] = (const __half (*)[HSTR])(stage + GEMM_A_HALFS);
#pragma unroll
        for (int kk = 0; kk < BK; kk += 16) {
            unsigned a[2][4];
#pragma unroll
            for (int mf = 0; mf < 2; mf++)
                ldsm_x4(a[mf][0], a[mf][1], a[mf][2], a[mf][3],
                        &As[wr * 32 + mf * 16 + lrow][kk + lcol]);
#pragma unroll
            for (int np = 0; np < 4; np++) {
                unsigned b0, b1, b2, b3;
                ldsm_x4(b0, b1, b2, b3, &Bs[wc * 64 + np * 16 + lrow][kk + lcol]);
#pragma unroll
                for (int mf = 0; mf < 2; mf++) {
                    mma_f16(acc[mf][2 * np][0], acc[mf][2 * np][1],
                            acc[mf][2 * np][2], acc[mf][2 * np][3],
                            a[mf][0], a[mf][1], a[mf][2], a[mf][3], b0, b2);
                    mma_f16(acc[mf][2 * np + 1][0], acc[mf][2 * np + 1][1],
                            acc[mf][2 * np + 1][2], acc[mf][2 * np + 1][3],
                            a[mf][0], a[mf][1], a[mf][2], a[mf][3], b1, b3);
                }
            }
        }
        __syncthreads();

        if (kt + 2 < 16) {
            gemm_load_stage(smem + ((kt + 2) % 3) * GEMM_STAGE_HALFS,
                            Ag + (kt + 2) * BK, Bg + (kt + 2) * BK, tid);
            cp_commit();
        }
    }
}

// Kernel 1: QKV projection. grid (64, 12). bn covers 256 cols of 3072.
__global__ __launch_bounds__(512, 1) void qkv_gemm_kernel() {
    extern __shared__ __half smem[];
    const int bm = blockIdx.x, bn = blockIdx.y;
    const int tid = threadIdx.x;
    const int warp = tid >> 5, lane = tid & 31;
    const int wr = warp >> 2, wc = warp & 3;
    const int g = lane >> 2, tig = lane & 3;

    float acc[2][8][4];
#pragma unroll
    for (int i = 0; i < 2; i++)
#pragma unroll
        for (int j = 0; j < 8; j++)
#pragma unroll
            for (int e = 0; e < 4; e++) acc[i][j][e] = 0.f;

    gemm_mainloop(smem, g_hh + (size_t)bm * 128 * DMODEL,
                  g_wqkvh + (size_t)bn * 256 * DMODEL, acc, tid);

    const int sec = bn >> 2;                 // 0=Q, 1=K, 2=V (256-col blocks)
    __half* dst = (sec == 0) ? g_Q : ((sec == 1) ? g_K : g_V);
#pragma unroll
    for (int mf = 0; mf < 2; mf++)
#pragma unroll
        for (int nf = 0; nf < 8; nf++)
#pragma unroll
            for (int eh = 0; eh < 2; eh++) {
                int rl = wr * 32 + mf * 16 + g + eh * 8;
                int cl = wc * 64 + nf * 8 + tig * 2;
                int m = bm * 128 + rl;
                int t = m >> 2, b = m & 3;
                int o = (bn & 3) * 256 + cl;           // 0..1023 within section
                int head = o >> 6, d = o & 63;
                unsigned pv = pack_h2(acc[mf][nf][eh * 2], acc[mf][nf][eh * 2 + 1]);
                *(unsigned*)(&dst[(((size_t)(b * NHEAD + head) * T_LEN + t) << 6) + d]) = pv;
            }
}

// Kernel 3a: out projection + residual. grid (64, 4).
__global__ __launch_bounds__(512, 1) void outproj_gemm_kernel(const float* __restrict__ hmat) {
    extern __shared__ __half smem[];
    const int bm = blockIdx.x, bn = blockIdx.y;
    const int tid = threadIdx.x;
    const int warp = tid >> 5, lane = tid & 31;
    const int wr = warp >> 2, wc = warp & 3;
    const int g = lane >> 2, tig = lane & 3;

    float acc[2][8][4];
#pragma unroll
    for (int i = 0; i < 2; i++)
#pragma unroll
        for (int j = 0; j < 8; j++)
#pragma unroll
            for (int e = 0; e < 4; e++) acc[i][j][e] = 0.f;

    gemm_mainloop(smem, g_att + (size_t)bm * 128 * DMODEL,
                  g_woh + (size_t)bn * 256 * DMODEL, acc, tid);

#pragma unroll
    for (int mf = 0; mf < 2; mf++)
#pragma unroll
        for (int nf = 0; nf < 8; nf++)
#pragma unroll
            for (int e = 0; e < 4; e++) {
                int rl = wr * 32 + mf * 16 + g + ((e >= 2) ? 8 : 0);
                int cl = wc * 64 + nf * 8 + tig * 2 + (e & 1);
                int m = bm * 128 + rl;
                int col = bn * 256 + cl;
                size_t idx = (size_t)m * DMODEL + col;
                g_res[idx] = acc[mf][nf][e] + hmat[idx];
            }
}

// ---------------------------------------------------------------------------
// Kernel 2: flash attention. 512 threads, 256 q-rows per CTA (16 warps x 16
// rows) sharing K/V tiles. 64-key chunks, hoisted Q frags, log2 softmax.
// grid (8 qblocks, 64 bh). 1 CTA/SM.
// ---------------------------------------------------------------------------
#define KV_STAGE_HALFS (128 * HSTR)              // 9216
#define FLASH_Q_OFF 0                            // 256 x HSTR = 18432 halves
#define FLASH_K_OFF (256 * HSTR)
#define FLASH_V_OFF (FLASH_K_OFF + 2 * KV_STAGE_HALFS)
#define FLASH_MSK_OFF (FLASH_V_OFF + 2 * KV_STAGE_HALFS)   // halves
#define FLASH_SMEM_BYTES (FLASH_MSK_OFF * 2 + 2 * 128 * 4 + 256)

__device__ __forceinline__ void flash_load_kv(__half* Kdst, __half* Vdst,
                                              const __half* Kg, const __half* Vg,
                                              int tid) {
#pragma unroll
    for (int i = 0; i < 2; i++) {                // 1024 chunks per matrix
        int s = tid + i * 512;
        int r = s >> 3, c8 = (s & 7) << 3;
        cp16(Kdst + r * HSTR + c8, Kg + (size_t)r * DHEAD + c8);
        cp16(Vdst + r * HSTR + c8, Vg + (size_t)r * DHEAD + c8);
    }
}

__global__ __launch_bounds__(512, 1) void flash_attn_kernel() {
    extern __shared__ __half sm[];
    __half (*Qs)[HSTR] = (__half (*)[HSTR])(sm + FLASH_Q_OFF);
    __half* Kbase = sm + FLASH_K_OFF;
    __half* Vbase = sm + FLASH_V_OFF;
    float* mfbase = (float*)(sm + FLASH_MSK_OFF);

    const int qb = blockIdx.x, bh = blockIdx.y;
    const int b = bh >> 4, hh = bh & 15;
    const int tid = threadIdx.x;
    const int warp = tid >> 5, lane = tid & 31;
    const int g = lane >> 2, tig = lane & 3;
    const int lrow = lane & 15, lcol = (lane >> 4) << 3;
    const int row0 = warp * 16;

    const __half* Qg = g_Q + (size_t)bh * T_LEN * DHEAD + (size_t)qb * 256 * DHEAD;
    const __half* Kg = g_K + (size_t)bh * T_LEN * DHEAD;
    const __half* Vg = g_V + (size_t)bh * T_LEN * DHEAD;
    const float* Mg = g_mskf + (size_t)b * T_LEN;

    // Stage 0 of K/V/mask first (get loads in flight)
    flash_load_kv(Kbase, Vbase, Kg, Vg, tid);
    if (tid < 32) cp16(mfbase + tid * 4, Mg + tid * 4);
    cp_commit();

    // Load Q tile (256x64) pre-scaled by SCALE*log2e
    const __half2 qs2 = __float2half2_rn(QSCALE_LOG2E);
#pragma unroll
    for (int i = 0; i < 4; i++) {                // 2048 chunks
        int s = tid + i * 512;
        int r = s >> 3, c8 = (s & 7) << 3;
        uint4 u = *(const uint4*)(Qg + (size_t)r * DHEAD + c8);
        __half2* hp = (__half2*)&u;
#pragma unroll
        for (int q = 0; q < 4; q++) hp[q] = __hmul2(hp[q], qs2);
        *(uint4*)(&Qs[r][c8]) = u;
    }
    __syncthreads();

    // Hoist Q fragments (invariant across all k-blocks)
    unsigned qf[4][4];
#pragma unroll
    for (int kk = 0; kk < 4; kk++)
        ldsm_x4(qf[kk][0], qf[kk][1], qf[kk][2], qf[kk][3],
                &Qs[row0 + lrow][kk * 16 + lcol]);

    float m_i[2] = {NEG_INF, NEG_INF};
    float l_i[2] = {0.f, 0.f};
    float o_acc[8][4];
#pragma unroll
    for (int nf = 0; nf < 8; nf++)
#pragma unroll
        for (int e = 0; e < 4; e++) o_acc[nf][e] = 0.f;

    for (int kb = 0; kb < 16; kb++) {
        if (kb + 1 < 16) {
            int st = (kb + 1) & 1;
            flash_load_kv(Kbase + st * KV_STAGE_HALFS, Vbase + st * KV_STAGE_HALFS,
                          Kg + (size_t)(kb + 1) * 128 * DHEAD,
                          Vg + (size_t)(kb + 1) * 128 * DHEAD, tid);
            if (tid < 32) cp16(mfbase + st * 128 + tid * 4, Mg + (kb + 1) * 128 + tid * 4);
            cp_commit();
            cp_wait<1>();
        } else {
            cp_wait<0>();
        }
        __syncthreads();

        const int st = kb & 1;
        const __half (*Ks)[HSTR] = (const __half (*)[HSTR])(Kbase + st * KV_STAGE_HALFS);
        const __half (*Vs)[HSTR] = (const __half (*)[HSTR])(Vbase + st * KV_STAGE_HALFS);
        const float* mskf = mfbase + st * 128;

#pragma unroll
        for (int half = 0; half < 2; half++) {
            const int base = half * 64;

            float s_acc[8][4];
#pragma unroll
            for (int nf = 0; nf < 8; nf++)
#pragma unroll
                for (int e = 0; e < 4; e++) s_acc[nf][e] = 0.f;
#pragma unroll
            for (int kk = 0; kk < 4; kk++) {
#pragma unroll
                for (int np = 0; np < 4; np++) {
                    unsigned b0, b1, b2, b3;
                    ldsm_x4(b0, b1, b2, b3,
                            &Ks[base + np * 16 + lrow][kk * 16 + lcol]);
                    mma_f16(s_acc[2 * np][0], s_acc[2 * np][1],
                            s_acc[2 * np][2], s_acc[2 * np][3],
                            qf[kk][0], qf[kk][1], qf[kk][2], qf[kk][3], b0, b2);
                    mma_f16(s_acc[2 * np + 1][0], s_acc[2 * np + 1][1],
                            s_acc[2 * np + 1][2], s_acc[2 * np + 1][3],
                            qf[kk][0], qf[kk][1], qf[kk][2], qf[kk][3], b1, b3);
                }
            }

            float mx[2] = {NEG_INF, NEG_INF};
#pragma unroll
            for (int nf = 0; nf < 8; nf++) {
                int c0 = base + nf * 8 + tig * 2;
                float2 mm = *(const float2*)(&mskf[c0]);
                s_acc[nf][0] += mm.x;
                s_acc[nf][1] += mm.y;
                s_acc[nf][2] += mm.x;
                s_acc[nf][3] += mm.y;
                mx[0] = fmaxf(mx[0], fmaxf(s_acc[nf][0], s_acc[nf][1]));
                mx[1] = fmaxf(mx[1], fmaxf(s_acc[nf][2], s_acc[nf][3]));
            }
#pragma unroll
            for (int off = 1; off < 4; off <<= 1) {
                mx[0] = fmaxf(mx[0], __shfl_xor_sync(0xffffffffu, mx[0], off));
                mx[1] = fmaxf(mx[1], __shfl_xor_sync(0xffffffffu, mx[1], off));
            }

            float alpha[2], mc[2];
#pragma unroll
            for (int r = 0; r < 2; r++) {
                float mnew = fmaxf(m_i[r], mx[r]);
                alpha[r] = ex2(clamp_m(m_i[r]) - clamp_m(mnew));
                m_i[r] = mnew;
                mc[r] = clamp_m(mnew);
            }

            unsigned pA[8][2];
            float ps[2] = {0.f, 0.f};
#pragma unroll
            for (int nf = 0; nf < 8; nf++) {
                float p0 = ex2(s_acc[nf][0] - mc[0]);
                float p1 = ex2(s_acc[nf][1] - mc[0]);
                float p2 = ex2(s_acc[nf][2] - mc[1]);
                float p3 = ex2(s_acc[nf][3] - mc[1]);
                ps[0] += p0 + p1;
                ps[1] += p2 + p3;
                pA[nf][0] = pack_h2(p0, p1);
                pA[nf][1] = pack_h2(p2, p3);
            }
#pragma unroll
            for (int off = 1; off < 4; off <<= 1) {
                ps[0] += __shfl_xor_sync(0xffffffffu, ps[0], off);
                ps[1] += __shfl_xor_sync(0xffffffffu, ps[1], off);
            }
            l_i[0] = l_i[0] * alpha[0] + ps[0];
            l_i[1] = l_i[1] * alpha[1] + ps[1];

#pragma unroll
            for (int nf = 0; nf < 8; nf++) {
                o_acc[nf][0] *= alpha[0];
                o_acc[nf][1] *= alpha[0];
                o_acc[nf][2] *= alpha[1];
                o_acc[nf][3] *= alpha[1];
            }

#pragma unroll
            for (int j = 0; j < 4; j++) {
                int kk = base + j * 16;
                unsigned a0 = pA[2 * j][0];
                unsigned a1 = pA[2 * j][1];
                unsigned a2 = pA[2 * j + 1][0];
                unsigned a3 = pA[2 * j + 1][1];
#pragma unroll
                for (int nfp = 0; nfp < 4; nfp++) {
                    int mt = lane >> 3, ri = lane & 7;
                    const __half* vp = &Vs[kk + ri + ((mt & 1) << 3)][nfp * 16 + ((mt >> 1) << 3)];
                    unsigned r0, r1, r2, r3;
                    ldsm_x4_trans(r0, r1, r2, r3, vp);
                    int nf = nfp * 2;
                    mma_f16(o_acc[nf][0], o_acc[nf][1], o_acc[nf][2], o_acc[nf][3],
                            a0, a1, a2, a3, r0, r1);
                    mma_f16(o_acc[nf + 1][0], o_acc[nf + 1][1], o_acc[nf + 1][2], o_acc[nf + 1][3],
                            a0, a1, a2, a3, r2, r3);
                }
            }
        }
        __syncthreads();
    }

    float inv_l[2] = {1.f / l_i[0], 1.f / l_i[1]};
#pragma unroll
    for (int nf = 0; nf < 8; nf++)
#pragma unroll
        for (int eh = 0; eh < 2; eh++) {
            int t = qb * 256 + row0 + g + eh * 8;
            int d = nf * 8 + tig * 2;
            int m = t * BATCH + b;
            unsigned pv = pack_h2(o_acc[nf][eh * 2] * inv_l[eh],
                                  o_acc[nf][eh * 2 + 1] * inv_l[eh]);
            *(unsigned*)(&g_att[(size_t)m * DMODEL + hh * DHEAD + d]) = pv;
        }
}

// ---------------------------------------------------------------------------
// Kernel 3b: LayerNorm per row (1024 elems), two-pass, register-resident.
// ---------------------------------------------------------------------------
__device__ __forceinline__ float block_sum256(float v) {
    __shared__ float red[8];
#pragma unroll
    for (int off = 16; off > 0; off >>= 1) v += __shfl_xor_sync(0xffffffffu, v, off);
    if ((threadIdx.x & 31) == 0) red[threadIdx.x >> 5] = v;
    __syncthreads();
    v = red[0] + red[1] + red[2] + red[3] + red[4] + red[5] + red[6] + red[7];
    __syncthreads();
    return v;
}

__global__ __launch_bounds__(256) void layernorm_kernel(
    const float* __restrict__ lng, const float* __restrict__ lnb,
    float* __restrict__ out)
{
    const int row = blockIdx.x;
    const int tid = threadIdx.x;
    const float* x = g_res + (size_t)row * DMODEL;
    float4 v = *(const float4*)(x + tid * 4);
    float s = block_sum256(v.x + v.y + v.z + v.w);
    float mu = s * (1.f / DMODEL);
    float dx = v.x - mu, dy = v.y - mu, dz = v.z - mu, dw = v.w - mu;
    float sq = block_sum256(dx * dx + dy * dy + dz * dz + dw * dw);
    float var = sq * (1.f / DMODEL);
    float rstd = rsqrtf(var + 1e-5f);
    float4 gg = *(const float4*)(lng + tid * 4);
    float4 bb = *(const float4*)(lnb + tid * 4);
    float4 r;
    r.x = dx * rstd * gg.x + bb.x;
    r.y = dy * rstd * gg.y + bb.y;
    r.z = dz * rstd * gg.z + bb.z;
    r.w = dw * rstd * gg.w + bb.w;
    *(float4*)(out + (size_t)row * DMODEL + tid * 4) = r;
}

// ---------------------------------------------------------------------------
extern "C" void kernel_launch(void* const* d_in, const int* in_sizes, int n_in,
                              void* d_out, int out_size) {
    const float* h = (const float*)d_in[0];
    const int* mask = (const int*)d_in[1];
    const float* wq = (const float*)d_in[2];
    const float* wkv = (const float*)d_in[3];
    const float* wo = (const float*)d_in[4];
    const float* lng = (const float*)d_in[5];
    const float* lnb = (const float*)d_in[6];
    float* out = (float*)d_out;

    cudaFuncSetAttribute(flash_attn_kernel,
                         cudaFuncAttributeMaxDynamicSharedMemorySize, FLASH_SMEM_BYTES);
    cudaFuncSetAttribute(qkv_gemm_kernel,
                         cudaFuncAttributeMaxDynamicSharedMemorySize, GEMM_SMEM_BYTES);
    cudaFuncSetAttribute(outproj_gemm_kernel,
                         cudaFuncAttributeMaxDynamicSharedMemorySize, GEMM_SMEM_BYTES);

    conv_all_kernel<<<(TOT4 + T_LEN + 255) / 256, 256>>>(h, wq, wkv, wo, mask);
    qkv_gemm_kernel<<<dim3(64, 12), 512, GEMM_SMEM_BYTES>>>();
    flash_attn_kernel<<<dim3(8, 64), 512, FLASH_SMEM_BYTES>>>();
    outproj_gemm_kernel<<<dim3(64, 4), 512, GEMM_SMEM_BYTES>>>(h);
    layernorm_kernel<<<MROWS, 256>>>(lng, lnb, out);
}

// round 10
// speedup vs baseline: 1.1234x; 1.1234x over previous
#include <cuda_runtime.h>
#include <cuda_fp16.h>
#include <cstdint>

// ---------------------------------------------------------------------------
// MultiHeadAttn: T=2048, B=4, N_HEAD=16, D_HEAD=64, D_MODEL=1024
// Round 10: R6 base (best: 500us). GEMMs get a 3-stage cp.async ring with a
// single barrier per k-tile + LDSM fragment double-buffering. tcgen05 is NOT
// available (harness PTX target is sm_103, not sm_103a) -> HMMA path tuned.
// ---------------------------------------------------------------------------

#define T_LEN 2048
#define BATCH 4
#define NHEAD 16
#define DHEAD 64
#define DMODEL 1024
#define MROWS (T_LEN * BATCH)        // 8192
#define QSCALE_LOG2E 0.180336878f    // (1/sqrt(64)) * log2(e)
#define MASKF -1e38f

__device__ __half g_hh[MROWS * DMODEL];
__device__ __half g_wqkvh[3072 * DMODEL];
__device__ __half g_woh[DMODEL * DMODEL];
__device__ float  g_mskf[BATCH * T_LEN];                // 0 or -1e38, [b][t]
__device__ __half g_Q[BATCH * NHEAD * T_LEN * DHEAD];   // [bh][t][d]
__device__ __half g_K[BATCH * NHEAD * T_LEN * DHEAD];
__device__ __half g_V[BATCH * NHEAD * T_LEN * DHEAD];
__device__ __half g_att[MROWS * DMODEL];
__device__ float  g_res[MROWS * DMODEL];

#define NEG_INF __int_as_float(0xff800000)

__device__ __forceinline__ float clamp_m(float x) { return fmaxf(x, -1e30f); }

__device__ __forceinline__ float ex2(float x) {
    float r;
    asm("ex2.approx.ftz.f32 %0, %1;" : "=f"(r) : "f"(x));
    return r;
}

__device__ __forceinline__ void mma_f16(float& c0, float& c1, float& c2, float& c3,
                                        unsigned a0, unsigned a1, unsigned a2, unsigned a3,
                                        unsigned b0, unsigned b1) {
    asm volatile(
        "mma.sync.aligned.m16n8k16.row.col.f32.f16.f16.f32 "
        "{%0,%1,%2,%3},{%4,%5,%6,%7},{%8,%9},{%0,%1,%2,%3};"
        : "+f"(c0), "+f"(c1), "+f"(c2), "+f"(c3)
        : "r"(a0), "r"(a1), "r"(a2), "r"(a3), "r"(b0), "r"(b1));
}

__device__ __forceinline__ void ldsm_x4(unsigned& r0, unsigned& r1,
                                        unsigned& r2, unsigned& r3,
                                        const __half* p) {
    unsigned sa = (unsigned)__cvta_generic_to_shared(p);
    asm volatile("ldmatrix.sync.aligned.m8n8.x4.shared.b16 {%0,%1,%2,%3}, [%4];"
                 : "=r"(r0), "=r"(r1), "=r"(r2), "=r"(r3) : "r"(sa));
}

__device__ __forceinline__ void ldsm_x4_trans(unsigned& r0, unsigned& r1,
                                              unsigned& r2, unsigned& r3,
                                              const __half* p) {
    unsigned sa = (unsigned)__cvta_generic_to_shared(p);
    asm volatile("ldmatrix.sync.aligned.m8n8.x4.trans.shared.b16 {%0,%1,%2,%3}, [%4];"
                 : "=r"(r0), "=r"(r1), "=r"(r2), "=r"(r3) : "r"(sa));
}

__device__ __forceinline__ unsigned pack_h2(float a, float b) {
    __half2 h = __floats2half2_rn(a, b);
    return *(unsigned*)&h;
}

__device__ __forceinline__ void cp16(const void* smem_dst, const void* gsrc) {
    unsigned sa = (unsigned)__cvta_generic_to_shared(smem_dst);
    unsigned long long ga = (unsigned long long)__cvta_generic_to_global(gsrc);
    asm volatile("cp.async.cg.shared.global [%0], [%1], 16;" :: "r"(sa), "l"(ga));
}
__device__ __forceinline__ void cp_commit() { asm volatile("cp.async.commit_group;"); }
template <int N>
__device__ __forceinline__ void cp_wait() { asm volatile("cp.async.wait_group %0;" :: "n"(N)); }

// ---------------------------------------------------------------------------
// Kernel 0: fused dtype converts + mask->float pack
// ---------------------------------------------------------------------------
#define H4   (MROWS * DMODEL / 4)
#define WQ4  (1024 * DMODEL / 4)
#define WKV4 (2048 * DMODEL / 4)
#define WO4  (DMODEL * DMODEL / 4)
#define TOT4 (H4 + WQ4 + WKV4 + WO4)

__global__ __launch_bounds__(256) void conv_all_kernel(
    const float* __restrict__ h, const float* __restrict__ wq,
    const float* __restrict__ wkv, const float* __restrict__ wo,
    const int* __restrict__ mask)
{
    int i = blockIdx.x * 256 + threadIdx.x;
    if (i < TOT4) {
        const float* src;
        __half* dst;
        int off;
        if (i < H4) { src = h; dst = g_hh; off = i; }
        else if (i < H4 + WQ4) { src = wq; dst = g_wqkvh; off = i - H4; }
        else if (i < H4 + WQ4 + WKV4) { src = wkv; dst = g_wqkvh + 1024 * DMODEL; off = i - H4 - WQ4; }
        else { src = wo; dst = g_woh; off = i - H4 - WQ4 - WKV4; }
        float4 v = ((const float4*)src)[off];
        uint2 u = {pack_h2(v.x, v.y), pack_h2(v.z, v.w)};
        ((uint2*)dst)[off] = u;
    } else {
        int t = i - TOT4;
        if (t < T_LEN) {
#pragma unroll
            for (int b = 0; b < BATCH; b++)
                g_mskf[b * T_LEN + t] = (mask[t * BATCH + b] != 0) ? MASKF : 0.f;
        }
    }
}

// ---------------------------------------------------------------------------
// fp16 GEMM: BM=BN=128, BK=64, 256 threads (8 warps 4x2, warp tile 32x64).
// 3-stage cp.async ring, ONE barrier per k-tile, LDSM fragment double-buffer.
// ---------------------------------------------------------------------------
#define BK 64
#define HSTR 72
#define GEMM_STAGE_HALFS (2 * 128 * HSTR)            // A + B per stage: 18432
#define GEMM_SMEM_BYTES (3 * GEMM_STAGE_HALFS * 2)   // 110592

__device__ __forceinline__ void gemm_load_stage(__half* stage,
                                                const __half* Ag, const __half* Bg,
                                                int tid) {
    __half* As = stage;
    __half* Bs = stage + 128 * HSTR;
#pragma unroll
    for (int i = 0; i < 4; i++) {
        int s = tid + i * 256;
        int r = s >> 3, c8 = (s & 7) << 3;
        cp16(As + r * HSTR + c8, Ag + (size_t)r * DMODEL + c8);
        cp16(Bs + r * HSTR + c8, Bg + (size_t)r * DMODEL + c8);
    }
}

__device__ __forceinline__ void gemm_mainloop(__half* smem, const __half* Ag,
                                              const __half* Bg, float acc[2][8][4],
                                              int tid) {
    const int warp = tid >> 5, lane = tid & 31;
    const int wr = warp >> 1, wc = warp & 1;
    const int lrow = lane & 15, lcol = (lane >> 4) << 3;

    gemm_load_stage(smem, Ag, Bg, tid);
    cp_commit();
    gemm_load_stage(smem + GEMM_STAGE_HALFS, Ag + BK, Bg + BK, tid);
    cp_commit();

    for (int kt = 0; kt < 16; kt++) {
        if (kt < 15) { cp_wait<1>(); } else { cp_wait<0>(); }
        __syncthreads();   // stage kt visible; all warps done with stage kt-1

        // issue loads for kt+2 into the buffer freed at kt-1
        if (kt + 2 < 16) {
            gemm_load_stage(smem + ((kt + 2) % 3) * GEMM_STAGE_HALFS,
                            Ag + (kt + 2) * BK, Bg + (kt + 2) * BK, tid);
            cp_commit();
        }

        const __half* stage = smem + (kt % 3) * GEMM_STAGE_HALFS;
        const __half (*As)[HSTR] = (const __half (*)[HSTR])stage;
        const __half (*Bs)[HSTR] = (const __half (*)[HSTR])(stage + 128 * HSTR);

        // fragment double-buffer: prefetch kk+1 while issuing kk's MMAs
        unsigned af[2][8], bf[2][16];
        ldsm_x4(af[0][0], af[0][1], af[0][2], af[0][3], &As[wr * 32 + lrow][lcol]);
        ldsm_x4(af[0][4], af[0][5], af[0][6], af[0][7], &As[wr * 32 + 16 + lrow][lcol]);
#pragma unroll
        for (int np = 0; np < 4; np++)
            ldsm_x4(bf[0][np * 4], bf[0][np * 4 + 1], bf[0][np * 4 + 2], bf[0][np * 4 + 3],
                    &Bs[wc * 64 + np * 16 + lrow][lcol]);

#pragma unroll
        for (int kkb = 0; kkb < 4; kkb++) {
            const int cur = kkb & 1, nxt = cur ^ 1;
            if (kkb < 3) {
                const int kk2 = (kkb + 1) * 16;
                ldsm_x4(af[nxt][0], af[nxt][1], af[nxt][2], af[nxt][3],
                        &As[wr * 32 + lrow][kk2 + lcol]);
                ldsm_x4(af[nxt][4], af[nxt][5], af[nxt][6], af[nxt][7],
                        &As[wr * 32 + 16 + lrow][kk2 + lcol]);
#pragma unroll
                for (int np = 0; np < 4; np++)
                    ldsm_x4(bf[nxt][np * 4], bf[nxt][np * 4 + 1],
                            bf[nxt][np * 4 + 2], bf[nxt][np * 4 + 3],
                            &Bs[wc * 64 + np * 16 + lrow][kk2 + lcol]);
            }
#pragma unroll
            for (int np = 0; np < 4; np++) {
#pragma unroll
                for (int mf = 0; mf < 2; mf++) {
                    mma_f16(acc[mf][2 * np][0], acc[mf][2 * np][1],
                            acc[mf][2 * np][2], acc[mf][2 * np][3],
                            af[cur][mf * 4], af[cur][mf * 4 + 1],
                            af[cur][mf * 4 + 2], af[cur][mf * 4 + 3],
                            bf[cur][np * 4], bf[cur][np * 4 + 2]);
                    mma_f16(acc[mf][2 * np + 1][0], acc[mf][2 * np + 1][1],
                            acc[mf][2 * np + 1][2], acc[mf][2 * np + 1][3],
                            af[cur][mf * 4], af[cur][mf * 4 + 1],
                            af[cur][mf * 4 + 2], af[cur][mf * 4 + 3],
                            bf[cur][np * 4 + 1], bf[cur][np * 4 + 3]);
                }
            }
        }
    }
}

// Kernel 1: QKV projection. grid (64, 24): bn<8 -> Q, 8..15 -> K, 16..23 -> V
__global__ __launch_bounds__(256, 2) void qkv_gemm_kernel() {
    extern __shared__ __half smem[];
    const int bm = blockIdx.x, bn = blockIdx.y;
    const int tid = threadIdx.x;
    const int warp = tid >> 5, lane = tid & 31;
    const int wr = warp >> 1, wc = warp & 1;
    const int g = lane >> 2, tig = lane & 3;

    float acc[2][8][4];
#pragma unroll
    for (int i = 0; i < 2; i++)
#pragma unroll
        for (int j = 0; j < 8; j++)
#pragma unroll
            for (int e = 0; e < 4; e++) acc[i][j][e] = 0.f;

    gemm_mainloop(smem, g_hh + (size_t)bm * 128 * DMODEL,
                  g_wqkvh + (size_t)bn * 128 * DMODEL, acc, tid);

    const int sec = bn >> 3;
    __half* dst = (sec == 0) ? g_Q : ((sec == 1) ? g_K : g_V);
#pragma unroll
    for (int mf = 0; mf < 2; mf++)
#pragma unroll
        for (int nf = 0; nf < 8; nf++)
#pragma unroll
            for (int eh = 0; eh < 2; eh++) {
                int rl = wr * 32 + mf * 16 + g + eh * 8;
                int cl = wc * 64 + nf * 8 + tig * 2;
                int m = bm * 128 + rl;
                int t = m >> 2, b = m & 3;
                int o = (bn & 7) * 128 + cl;
                int head = o >> 6, d = o & 63;
                unsigned pv = pack_h2(acc[mf][nf][eh * 2], acc[mf][nf][eh * 2 + 1]);
                *(unsigned*)(&dst[(((size_t)(b * NHEAD + head) * T_LEN + t) << 6) + d]) = pv;
            }
}

// Kernel 3a: out projection + residual. grid (64, 8).
__global__ __launch_bounds__(256, 2) void outproj_gemm_kernel(const float* __restrict__ hmat) {
    extern __shared__ __half smem[];
    const int bm = blockIdx.x, bn = blockIdx.y;
    const int tid = threadIdx.x;
    const int warp = tid >> 5, lane = tid & 31;
    const int wr = warp >> 1, wc = warp & 1;
    const int g = lane >> 2, tig = lane & 3;

    float acc[2][8][4];
#pragma unroll
    for (int i = 0; i < 2; i++)
#pragma unroll
        for (int j = 0; j < 8; j++)
#pragma unroll
            for (int e = 0; e < 4; e++) acc[i][j][e] = 0.f;

    gemm_mainloop(smem, g_att + (size_t)bm * 128 * DMODEL,
                  g_woh + (size_t)bn * 128 * DMODEL, acc, tid);

#pragma unroll
    for (int mf = 0; mf < 2; mf++)
#pragma unroll
        for (int nf = 0; nf < 8; nf++)
#pragma unroll
            for (int e = 0; e < 4; e++) {
                int rl = wr * 32 + mf * 16 + g + ((e >= 2) ? 8 : 0);
                int cl = wc * 64 + nf * 8 + tig * 2 + (e & 1);
                int m = bm * 128 + rl;
                int col = bn * 128 + cl;
                size_t idx = (size_t)m * DMODEL + col;
                g_res[idx] = acc[mf][nf][e] + hmat[idx];
            }
}

// ---------------------------------------------------------------------------
// Kernel 2: flash attention (R6 proven). 256 threads, 2 CTA/SM.
// ---------------------------------------------------------------------------
#define KV_STAGE_HALFS (128 * HSTR)
#define FLASH_Q_OFF 0
#define FLASH_K_OFF (128 * HSTR)
#define FLASH_V_OFF (FLASH_K_OFF + 2 * KV_STAGE_HALFS)
#define FLASH_MSK_OFF (FLASH_V_OFF + 2 * KV_STAGE_HALFS)   // halves
#define FLASH_SMEM_BYTES (FLASH_MSK_OFF * 2 + 2 * 128 * 4 + 256)

__device__ __forceinline__ void flash_load_kv(__half* Kdst, __half* Vdst,
                                              const __half* Kg, const __half* Vg,
                                              int tid) {
#pragma unroll
    for (int i = 0; i < 4; i++) {
        int s = tid + i * 256;
        int r = s >> 3, c8 = (s & 7) << 3;
        cp16(Kdst + r * HSTR + c8, Kg + (size_t)r * DHEAD + c8);
        cp16(Vdst + r * HSTR + c8, Vg + (size_t)r * DHEAD + c8);
    }
}

__global__ __launch_bounds__(256, 2) void flash_attn_kernel() {
    extern __shared__ __half sm[];
    __half (*Qs)[HSTR] = (__half (*)[HSTR])(sm + FLASH_Q_OFF);
    __half* Kbase = sm + FLASH_K_OFF;
    __half* Vbase = sm + FLASH_V_OFF;
    float* mfbase = (float*)(sm + FLASH_MSK_OFF);

    const int qb = blockIdx.x, bh = blockIdx.y;
    const int b = bh >> 4, hh = bh & 15;
    const int tid = threadIdx.x;
    const int warp = tid >> 5, lane = tid & 31;
    const int g = lane >> 2, tig = lane & 3;
    const int lrow = lane & 15, lcol = (lane >> 4) << 3;
    const int row0 = warp * 16;

    const __half* Qg = g_Q + (size_t)bh * T_LEN * DHEAD + (size_t)qb * 128 * DHEAD;
    const __half* Kg = g_K + (size_t)bh * T_LEN * DHEAD;
    const __half* Vg = g_V + (size_t)bh * T_LEN * DHEAD;
    const float* Mg = g_mskf + (size_t)b * T_LEN;

    flash_load_kv(Kbase, Vbase, Kg, Vg, tid);
    if (tid < 32) cp16(mfbase + tid * 4, Mg + tid * 4);
    cp_commit();

    const __half2 qs2 = __float2half2_rn(QSCALE_LOG2E);
#pragma unroll
    for (int i = 0; i < 4; i++) {
        int s = tid + i * 256;
        int r = s >> 3, c8 = (s & 7) << 3;
        uint4 u = *(const uint4*)(Qg + (size_t)r * DHEAD + c8);
        __half2* hp = (__half2*)&u;
#pragma unroll
        for (int q = 0; q < 4; q++) hp[q] = __hmul2(hp[q], qs2);
        *(uint4*)(&Qs[r][c8]) = u;
    }
    __syncthreads();

    unsigned qf[4][4];
#pragma unroll
    for (int kk = 0; kk < 4; kk++)
        ldsm_x4(qf[kk][0], qf[kk][1], qf[kk][2], qf[kk][3],
                &Qs[row0 + lrow][kk * 16 + lcol]);

    float m_i[2] = {NEG_INF, NEG_INF};
    float l_i[2] = {0.f, 0.f};
    float o_acc[8][4];
#pragma unroll
    for (int nf = 0; nf < 8; nf++)
#pragma unroll
        for (int e = 0; e < 4; e++) o_acc[nf][e] = 0.f;

    for (int kb = 0; kb < 16; kb++) {
        if (kb + 1 < 16) {
            int st = (kb + 1) & 1;
            flash_load_kv(Kbase + st * KV_STAGE_HALFS, Vbase + st * KV_STAGE_HALFS,
                          Kg + (size_t)(kb + 1) * 128 * DHEAD,
                          Vg + (size_t)(kb + 1) * 128 * DHEAD, tid);
            if (tid < 32) cp16(mfbase + st * 128 + tid * 4, Mg + (kb + 1) * 128 + tid * 4);
            cp_commit();
            cp_wait<1>();
        } else {
            cp_wait<0>();
        }
        __syncthreads();

        const int st = kb & 1;
        const __half (*Ks)[HSTR] = (const __half (*)[HSTR])(Kbase + st * KV_STAGE_HALFS);
        const __half (*Vs)[HSTR] = (const __half (*)[HSTR])(Vbase + st * KV_STAGE_HALFS);
        const float* mskf = mfbase + st * 128;

#pragma unroll
        for (int half = 0; half < 2; half++) {
            const int base = half * 64;

            float s_acc[8][4];
#pragma unroll
            for (int nf = 0; nf < 8; nf++)
#pragma unroll
                for (int e = 0; e < 4; e++) s_acc[nf][e] = 0.f;
#pragma unroll
            for (int kk = 0; kk < 4; kk++) {
#pragma unroll
                for (int np = 0; np < 4; np++) {
                    unsigned b0, b1, b2, b3;
                    ldsm_x4(b0, b1, b2, b3,
                            &Ks[base + np * 16 + lrow][kk * 16 + lcol]);
                    mma_f16(s_acc[2 * np][0], s_acc[2 * np][1],
                            s_acc[2 * np][2], s_acc[2 * np][3],
                            qf[kk][0], qf[kk][1], qf[kk][2], qf[kk][3], b0, b2);
                    mma_f16(s_acc[2 * np + 1][0], s_acc[2 * np + 1][1],
                            s_acc[2 * np + 1][2], s_acc[2 * np + 1][3],
                            qf[kk][0], qf[kk][1], qf[kk][2], qf[kk][3], b1, b3);
                }
            }

            float mx[2] = {NEG_INF, NEG_INF};
#pragma unroll
            for (int nf = 0; nf < 8; nf++) {
                int c0 = base + nf * 8 + tig * 2;
                float2 mm = *(const float2*)(&mskf[c0]);
                s_acc[nf][0] += mm.x;
                s_acc[nf][1] += mm.y;
                s_acc[nf][2] += mm.x;
                s_acc[nf][3] += mm.y;
                mx[0] = fmaxf(mx[0], fmaxf(s_acc[nf][0], s_acc[nf][1]));
                mx[1] = fmaxf(mx[1], fmaxf(s_acc[nf][2], s_acc[nf][3]));
            }
#pragma unroll
            for (int off = 1; off < 4; off <<= 1) {
                mx[0] = fmaxf(mx[0], __shfl_xor_sync(0xffffffffu, mx[0], off));
                mx[1] = fmaxf(mx[1], __shfl_xor_sync(0xffffffffu, mx[1], off));
            }

            float alpha[2], mc[2];
#pragma unroll
            for (int r = 0; r < 2; r++) {
                float mnew = fmaxf(m_i[r], mx[r]);
                alpha[r] = ex2(clamp_m(m_i[r]) - clamp_m(mnew));
                m_i[r] = mnew;
                mc[r] = clamp_m(mnew);
            }

            unsigned pA[8][2];
            float ps[2] = {0.f, 0.f};
#pragma unroll
            for (int nf = 0; nf < 8; nf++) {
                float p0 = ex2(s_acc[nf][0] - mc[0]);
                float p1 = ex2(s_acc[nf][1] - mc[0]);
                float p2 = ex2(s_acc[nf][2] - mc[1]);
                float p3 = ex2(s_acc[nf][3] - mc[1]);
                ps[0] += p0 + p1;
                ps[1] += p2 + p3;
                pA[nf][0] = pack_h2(p0, p1);
                pA[nf][1] = pack_h2(p2, p3);
            }
#pragma unroll
            for (int off = 1; off < 4; off <<= 1) {
                ps[0] += __shfl_xor_sync(0xffffffffu, ps[0], off);
                ps[1] += __shfl_xor_sync(0xffffffffu, ps[1], off);
            }
            l_i[0] = l_i[0] * alpha[0] + ps[0];
            l_i[1] = l_i[1] * alpha[1] + ps[1];

#pragma unroll
            for (int nf = 0; nf < 8; nf++) {
                o_acc[nf][0] *= alpha[0];
                o_acc[nf][1] *= alpha[0];
                o_acc[nf][2] *= alpha[1];
                o_acc[nf][3] *= alpha[1];
            }

#pragma unroll
            for (int j = 0; j < 4; j++) {
                int kk = base + j * 16;
                unsigned a0 = pA[2 * j][0];
                unsigned a1 = pA[2 * j][1];
                unsigned a2 = pA[2 * j + 1][0];
                unsigned a3 = pA[2 * j + 1][1];
#pragma unroll
                for (int nfp = 0; nfp < 4; nfp++) {
                    int mt = lane >> 3, ri = lane & 7;
                    const __half* vp = &Vs[kk + ri + ((mt & 1) << 3)][nfp * 16 + ((mt >> 1) << 3)];
                    unsigned r0, r1, r2, r3;
                    ldsm_x4_trans(r0, r1, r2, r3, vp);
                    int nf = nfp * 2;
                    mma_f16(o_acc[nf][0], o_acc[nf][1], o_acc[nf][2], o_acc[nf][3],
                            a0, a1, a2, a3, r0, r1);
                    mma_f16(o_acc[nf + 1][0], o_acc[nf + 1][1], o_acc[nf + 1][2], o_acc[nf + 1][3],
                            a0, a1, a2, a3, r2, r3);
                }
            }
        }
        __syncthreads();
    }

    float inv_l[2] = {1.f / l_i[0], 1.f / l_i[1]};
#pragma unroll
    for (int nf = 0; nf < 8; nf++)
#pragma unroll
        for (int eh = 0; eh < 2; eh++) {
            int t = qb * 128 + row0 + g + eh * 8;
            int d = nf * 8 + tig * 2;
            int m = t * BATCH + b;
            unsigned pv = pack_h2(o_acc[nf][eh * 2] * inv_l[eh],
                                  o_acc[nf][eh * 2 + 1] * inv_l[eh]);
            *(unsigned*)(&g_att[(size_t)m * DMODEL + hh * DHEAD + d]) = pv;
        }
}

// ---------------------------------------------------------------------------
// Kernel 3b: LayerNorm per row (1024 elems), two-pass, register-resident.
// ---------------------------------------------------------------------------
__device__ __forceinline__ float block_sum256(float v) {
    __shared__ float red[8];
#pragma unroll
    for (int off = 16; off > 0; off >>= 1) v += __shfl_xor_sync(0xffffffffu, v, off);
    if ((threadIdx.x & 31) == 0) red[threadIdx.x >> 5] = v;
    __syncthreads();
    v = red[0] + red[1] + red[2] + red[3] + red[4] + red[5] + red[6] + red[7];
    __syncthreads();
    return v;
}

__global__ __launch_bounds__(256) void layernorm_kernel(
    const float* __restrict__ lng, const float* __restrict__ lnb,
    float* __restrict__ out)
{
    const int row = blockIdx.x;
    const int tid = threadIdx.x;
    const float* x = g_res + (size_t)row * DMODEL;
    float4 v = *(const float4*)(x + tid * 4);
    float s = block_sum256(v.x + v.y + v.z + v.w);
    float mu = s * (1.f / DMODEL);
    float dx = v.x - mu, dy = v.y - mu, dz = v.z - mu, dw = v.w - mu;
    float sq = block_sum256(dx * dx + dy * dy + dz * dz + dw * dw);
    float var = sq * (1.f / DMODEL);
    float rstd = rsqrtf(var + 1e-5f);
    float4 gg = *(const float4*)(lng + tid * 4);
    float4 bb = *(const float4*)(lnb + tid * 4);
    float4 r;
    r.x = dx * rstd * gg.x + bb.x;
    r.y = dy * rstd * gg.y + bb.y;
    r.z = dz * rstd * gg.z + bb.z;
    r.w = dw * rstd * gg.w + bb.w;
    *(float4*)(out + (size_t)row * DMODEL + tid * 4) = r;
}

// ---------------------------------------------------------------------------
extern "C" void kernel_launch(void* const* d_in, const int* in_sizes, int n_in,
                              void* d_out, int out_size) {
    const float* h = (const float*)d_in[0];
    const int* mask = (const int*)d_in[1];
    const float* wq = (const float*)d_in[2];
    const float* wkv = (const float*)d_in[3];
    const float* wo = (const float*)d_in[4];
    const float* lng = (const float*)d_in[5];
    const float* lnb = (const float*)d_in[6];
    float* out = (float*)d_out;

    cudaFuncSetAttribute(flash_attn_kernel,
                         cudaFuncAttributeMaxDynamicSharedMemorySize, FLASH_SMEM_BYTES);
    cudaFuncSetAttribute(qkv_gemm_kernel,
                         cudaFuncAttributeMaxDynamicSharedMemorySize, GEMM_SMEM_BYTES);
    cudaFuncSetAttribute(outproj_gemm_kernel,
                         cudaFuncAttributeMaxDynamicSharedMemorySize, GEMM_SMEM_BYTES);

    conv_all_kernel<<<(TOT4 + T_LEN + 255) / 256, 256>>>(h, wq, wkv, wo, mask);
    qkv_gemm_kernel<<<dim3(64, 24), 256, GEMM_SMEM_BYTES>>>();
    flash_attn_kernel<<<dim3(16, 64), 256, FLASH_SMEM_BYTES>>>();
    outproj_gemm_kernel<<<dim3(64, 8), 256, GEMM_SMEM_BYTES>>>(h);
    layernorm_kernel<<<MROWS, 256>>>(lng, lnb, out);
}

// round 11
// speedup vs baseline: 1.1528x; 1.0262x over previous
#include <cuda_runtime.h>
#include <cuda_fp16.h>
#include <cstdint>

// ---------------------------------------------------------------------------
// MultiHeadAttn: T=2048, B=4, N_HEAD=16, D_HEAD=64, D_MODEL=1024
// Round 11: GEMMs use 128-thread CTAs (BM=64,BN=128, same 32x64 warp tile,
// 128 regs) -> 4 CTAs/SM = 16 resident warps (vs 8). Flash/conv/LN = R6.
// tcgen05 unavailable (harness PTX target sm_103, not sm_103a).
// ---------------------------------------------------------------------------

#define T_LEN 2048
#define BATCH 4
#define NHEAD 16
#define DHEAD 64
#define DMODEL 1024
#define MROWS (T_LEN * BATCH)        // 8192
#define QSCALE_LOG2E 0.180336878f    // (1/sqrt(64)) * log2(e)
#define MASKF -1e38f

__device__ __half g_hh[MROWS * DMODEL];
__device__ __half g_wqkvh[3072 * DMODEL];
__device__ __half g_woh[DMODEL * DMODEL];
__device__ float  g_mskf[BATCH * T_LEN];                // 0 or -1e38, [b][t]
__device__ __half g_Q[BATCH * NHEAD * T_LEN * DHEAD];   // [bh][t][d]
__device__ __half g_K[BATCH * NHEAD * T_LEN * DHEAD];
__device__ __half g_V[BATCH * NHEAD * T_LEN * DHEAD];
__device__ __half g_att[MROWS * DMODEL];
__device__ float  g_res[MROWS * DMODEL];

#define NEG_INF __int_as_float(0xff800000)

__device__ __forceinline__ float clamp_m(float x) { return fmaxf(x, -1e30f); }

__device__ __forceinline__ float ex2(float x) {
    float r;
    asm("ex2.approx.ftz.f32 %0, %1;" : "=f"(r) : "f"(x));
    return r;
}

__device__ __forceinline__ void mma_f16(float& c0, float& c1, float& c2, float& c3,
                                        unsigned a0, unsigned a1, unsigned a2, unsigned a3,
                                        unsigned b0, unsigned b1) {
    asm volatile(
        "mma.sync.aligned.m16n8k16.row.col.f32.f16.f16.f32 "
        "{%0,%1,%2,%3},{%4,%5,%6,%7},{%8,%9},{%0,%1,%2,%3};"
        : "+f"(c0), "+f"(c1), "+f"(c2), "+f"(c3)
        : "r"(a0), "r"(a1), "r"(a2), "r"(a3), "r"(b0), "r"(b1));
}

__device__ __forceinline__ void ldsm_x4(unsigned& r0, unsigned& r1,
                                        unsigned& r2, unsigned& r3,
                                        const __half* p) {
    unsigned sa = (unsigned)__cvta_generic_to_shared(p);
    asm volatile("ldmatrix.sync.aligned.m8n8.x4.shared.b16 {%0,%1,%2,%3}, [%4];"
                 : "=r"(r0), "=r"(r1), "=r"(r2), "=r"(r3) : "r"(sa));
}

__device__ __forceinline__ void ldsm_x4_trans(unsigned& r0, unsigned& r1,
                                              unsigned& r2, unsigned& r3,
                                              const __half* p) {
    unsigned sa = (unsigned)__cvta_generic_to_shared(p);
    asm volatile("ldmatrix.sync.aligned.m8n8.x4.trans.shared.b16 {%0,%1,%2,%3}, [%4];"
                 : "=r"(r0), "=r"(r1), "=r"(r2), "=r"(r3) : "r"(sa));
}

__device__ __forceinline__ unsigned pack_h2(float a, float b) {
    __half2 h = __floats2half2_rn(a, b);
    return *(unsigned*)&h;
}

__device__ __forceinline__ void cp16(const void* smem_dst, const void* gsrc) {
    unsigned sa = (unsigned)__cvta_generic_to_shared(smem_dst);
    unsigned long long ga = (unsigned long long)__cvta_generic_to_global(gsrc);
    asm volatile("cp.async.cg.shared.global [%0], [%1], 16;" :: "r"(sa), "l"(ga));
}
__device__ __forceinline__ void cp_commit() { asm volatile("cp.async.commit_group;"); }
template <int N>
__device__ __forceinline__ void cp_wait() { asm volatile("cp.async.wait_group %0;" :: "n"(N)); }

// ---------------------------------------------------------------------------
// Kernel 0: fused dtype converts + mask->float pack
// ---------------------------------------------------------------------------
#define H4   (MROWS * DMODEL / 4)
#define WQ4  (1024 * DMODEL / 4)
#define WKV4 (2048 * DMODEL / 4)
#define WO4  (DMODEL * DMODEL / 4)
#define TOT4 (H4 + WQ4 + WKV4 + WO4)

__global__ __launch_bounds__(256) void conv_all_kernel(
    const float* __restrict__ h, const float* __restrict__ wq,
    const float* __restrict__ wkv, const float* __restrict__ wo,
    const int* __restrict__ mask)
{
    int i = blockIdx.x * 256 + threadIdx.x;
    if (i < TOT4) {
        const float* src;
        __half* dst;
        int off;
        if (i < H4) { src = h; dst = g_hh; off = i; }
        else if (i < H4 + WQ4) { src = wq; dst = g_wqkvh; off = i - H4; }
        else if (i < H4 + WQ4 + WKV4) { src = wkv; dst = g_wqkvh + 1024 * DMODEL; off = i - H4 - WQ4; }
        else { src = wo; dst = g_woh; off = i - H4 - WQ4 - WKV4; }
        float4 v = ((const float4*)src)[off];
        uint2 u = {pack_h2(v.x, v.y), pack_h2(v.z, v.w)};
        ((uint2*)dst)[off] = u;
    } else {
        int t = i - TOT4;
        if (t < T_LEN) {
#pragma unroll
            for (int b = 0; b < BATCH; b++)
                g_mskf[b * T_LEN + t] = (mask[t * BATCH + b] != 0) ? MASKF : 0.f;
        }
    }
}

// ---------------------------------------------------------------------------
// fp16 GEMM: BM=64, BN=128, BK=64; 128 threads (4 warps as 2x2, warp tile
// 32x64). 2-stage cp.async ring. 4 CTAs/SM.
// ---------------------------------------------------------------------------
#define BK 64
#define HSTR 72
#define GEMM_A_HALFS (64 * HSTR)                     // 4608
#define GEMM_STAGE_HALFS ((64 + 128) * HSTR)         // 13824
#define GEMM_SMEM_BYTES (2 * GEMM_STAGE_HALFS * 2)   // 55296

__device__ __forceinline__ void gemm_load_stage(__half* stage,
                                                const __half* Ag, const __half* Bg,
                                                int tid) {
    __half* As = stage;
    __half* Bs = stage + GEMM_A_HALFS;
#pragma unroll
    for (int i = 0; i < 4; i++) {                 // A: 512 chunks (64 rows x 8)
        int s = tid + i * 128;
        int r = s >> 3, c8 = (s & 7) << 3;
        cp16(As + r * HSTR + c8, Ag + (size_t)r * DMODEL + c8);
    }
#pragma unroll
    for (int i = 0; i < 8; i++) {                 // B: 1024 chunks (128 rows x 8)
        int s = tid + i * 128;
        int r = s >> 3, c8 = (s & 7) << 3;
        cp16(Bs + r * HSTR + c8, Bg + (size_t)r * DMODEL + c8);
    }
}

__device__ __forceinline__ void gemm_mainloop(__half* smem, const __half* Ag,
                                              const __half* Bg, float acc[2][8][4],
                                              int tid) {
    const int warp = tid >> 5, lane = tid & 31;
    const int wr = warp >> 1, wc = warp & 1;
    const int lrow = lane & 15, lcol = (lane >> 4) << 3;

    gemm_load_stage(smem, Ag, Bg, tid);
    cp_commit();

    for (int kt = 0; kt < 16; kt++) {
        if (kt + 1 < 16) {
            gemm_load_stage(smem + ((kt + 1) & 1) * GEMM_STAGE_HALFS,
                            Ag + (kt + 1) * BK, Bg + (kt + 1) * BK, tid);
            cp_commit();
            cp_wait<1>();
        } else {
            cp_wait<0>();
        }
        __syncthreads();

        const __half* stage = smem + (kt & 1) * GEMM_STAGE_HALFS;
        const __half (*As)[HSTR] = (const __half (*)[HSTR])stage;
        const __half (*Bs)[HSTR] = (const __half (*)[HSTR])(stage + GEMM_A_HALFS);
#pragma unroll
        for (int kk = 0; kk < BK; kk += 16) {
            unsigned a[2][4];
#pragma unroll
            for (int mf = 0; mf < 2; mf++)
                ldsm_x4(a[mf][0], a[mf][1], a[mf][2], a[mf][3],
                        &As[wr * 32 + mf * 16 + lrow][kk + lcol]);
#pragma unroll
            for (int np = 0; np < 4; np++) {
                unsigned b0, b1, b2, b3;
                ldsm_x4(b0, b1, b2, b3, &Bs[wc * 64 + np * 16 + lrow][kk + lcol]);
#pragma unroll
                for (int mf = 0; mf < 2; mf++) {
                    mma_f16(acc[mf][2 * np][0], acc[mf][2 * np][1],
                            acc[mf][2 * np][2], acc[mf][2 * np][3],
                            a[mf][0], a[mf][1], a[mf][2], a[mf][3], b0, b2);
                    mma_f16(acc[mf][2 * np + 1][0], acc[mf][2 * np + 1][1],
                            acc[mf][2 * np + 1][2], acc[mf][2 * np + 1][3],
                            a[mf][0], a[mf][1], a[mf][2], a[mf][3], b1, b3);
                }
            }
        }
        __syncthreads();
    }
}

// Kernel 1: QKV projection. grid (128, 24): bn<8 -> Q, 8..15 -> K, 16..23 -> V
__global__ __launch_bounds__(128, 4) void qkv_gemm_kernel() {
    extern __shared__ __half smem[];
    const int bm = blockIdx.x, bn = blockIdx.y;
    const int tid = threadIdx.x;
    const int warp = tid >> 5, lane = tid & 31;
    const int wr = warp >> 1, wc = warp & 1;
    const int g = lane >> 2, tig = lane & 3;

    float acc[2][8][4];
#pragma unroll
    for (int i = 0; i < 2; i++)
#pragma unroll
        for (int j = 0; j < 8; j++)
#pragma unroll
            for (int e = 0; e < 4; e++) acc[i][j][e] = 0.f;

    gemm_mainloop(smem, g_hh + (size_t)bm * 64 * DMODEL,
                  g_wqkvh + (size_t)bn * 128 * DMODEL, acc, tid);

    const int sec = bn >> 3;
    __half* dst = (sec == 0) ? g_Q : ((sec == 1) ? g_K : g_V);
#pragma unroll
    for (int mf = 0; mf < 2; mf++)
#pragma unroll
        for (int nf = 0; nf < 8; nf++)
#pragma unroll
            for (int eh = 0; eh < 2; eh++) {
                int rl = wr * 32 + mf * 16 + g + eh * 8;
                int cl = wc * 64 + nf * 8 + tig * 2;
                int m = bm * 64 + rl;
                int t = m >> 2, b = m & 3;
                int o = (bn & 7) * 128 + cl;
                int head = o >> 6, d = o & 63;
                unsigned pv = pack_h2(acc[mf][nf][eh * 2], acc[mf][nf][eh * 2 + 1]);
                *(unsigned*)(&dst[(((size_t)(b * NHEAD + head) * T_LEN + t) << 6) + d]) = pv;
            }
}

// Kernel 3a: out projection + residual. grid (128, 8).
__global__ __launch_bounds__(128, 4) void outproj_gemm_kernel(const float* __restrict__ hmat) {
    extern __shared__ __half smem[];
    const int bm = blockIdx.x, bn = blockIdx.y;
    const int tid = threadIdx.x;
    const int warp = tid >> 5, lane = tid & 31;
    const int wr = warp >> 1, wc = warp & 1;
    const int g = lane >> 2, tig = lane & 3;

    float acc[2][8][4];
#pragma unroll
    for (int i = 0; i < 2; i++)
#pragma unroll
        for (int j = 0; j < 8; j++)
#pragma unroll
            for (int e = 0; e < 4; e++) acc[i][j][e] = 0.f;

    gemm_mainloop(smem, g_att + (size_t)bm * 64 * DMODEL,
                  g_woh + (size_t)bn * 128 * DMODEL, acc, tid);

#pragma unroll
    for (int mf = 0; mf < 2; mf++)
#pragma unroll
        for (int nf = 0; nf < 8; nf++)
#pragma unroll
            for (int e = 0; e < 4; e++) {
                int rl = wr * 32 + mf * 16 + g + ((e >= 2) ? 8 : 0);
                int cl = wc * 64 + nf * 8 + tig * 2 + (e & 1);
                int m = bm * 64 + rl;
                int col = bn * 128 + cl;
                size_t idx = (size_t)m * DMODEL + col;
                g_res[idx] = acc[mf][nf][e] + hmat[idx];
            }
}

// ---------------------------------------------------------------------------
// Kernel 2: flash attention (R6 proven). 256 threads, 2 CTA/SM.
// ---------------------------------------------------------------------------
#define KV_STAGE_HALFS (128 * HSTR)
#define FLASH_Q_OFF 0
#define FLASH_K_OFF (128 * HSTR)
#define FLASH_V_OFF (FLASH_K_OFF + 2 * KV_STAGE_HALFS)
#define FLASH_MSK_OFF (FLASH_V_OFF + 2 * KV_STAGE_HALFS)   // halves
#define FLASH_SMEM_BYTES (FLASH_MSK_OFF * 2 + 2 * 128 * 4 + 256)

__device__ __forceinline__ void flash_load_kv(__half* Kdst, __half* Vdst,
                                              const __half* Kg, const __half* Vg,
                                              int tid) {
#pragma unroll
    for (int i = 0; i < 4; i++) {
        int s = tid + i * 256;
        int r = s >> 3, c8 = (s & 7) << 3;
        cp16(Kdst + r * HSTR + c8, Kg + (size_t)r * DHEAD + c8);
        cp16(Vdst + r * HSTR + c8, Vg + (size_t)r * DHEAD + c8);
    }
}

__global__ __launch_bounds__(256, 2) void flash_attn_kernel() {
    extern __shared__ __half sm[];
    __half (*Qs)[HSTR] = (__half (*)[HSTR])(sm + FLASH_Q_OFF);
    __half* Kbase = sm + FLASH_K_OFF;
    __half* Vbase = sm + FLASH_V_OFF;
    float* mfbase = (float*)(sm + FLASH_MSK_OFF);

    const int qb = blockIdx.x, bh = blockIdx.y;
    const int b = bh >> 4, hh = bh & 15;
    const int tid = threadIdx.x;
    const int warp = tid >> 5, lane = tid & 31;
    const int g = lane >> 2, tig = lane & 3;
    const int lrow = lane & 15, lcol = (lane >> 4) << 3;
    const int row0 = warp * 16;

    const __half* Qg = g_Q + (size_t)bh * T_LEN * DHEAD + (size_t)qb * 128 * DHEAD;
    const __half* Kg = g_K + (size_t)bh * T_LEN * DHEAD;
    const __half* Vg = g_V + (size_t)bh * T_LEN * DHEAD;
    const float* Mg = g_mskf + (size_t)b * T_LEN;

    flash_load_kv(Kbase, Vbase, Kg, Vg, tid);
    if (tid < 32) cp16(mfbase + tid * 4, Mg + tid * 4);
    cp_commit();

    const __half2 qs2 = __float2half2_rn(QSCALE_LOG2E);
#pragma unroll
    for (int i = 0; i < 4; i++) {
        int s = tid + i * 256;
        int r = s >> 3, c8 = (s & 7) << 3;
        uint4 u = *(const uint4*)(Qg + (size_t)r * DHEAD + c8);
        __half2* hp = (__half2*)&u;
#pragma unroll
        for (int q = 0; q < 4; q++) hp[q] = __hmul2(hp[q], qs2);
        *(uint4*)(&Qs[r][c8]) = u;
    }
    __syncthreads();

    unsigned qf[4][4];
#pragma unroll
    for (int kk = 0; kk < 4; kk++)
        ldsm_x4(qf[kk][0], qf[kk][1], qf[kk][2], qf[kk][3],
                &Qs[row0 + lrow][kk * 16 + lcol]);

    float m_i[2] = {NEG_INF, NEG_INF};
    float l_i[2] = {0.f, 0.f};
    float o_acc[8][4];
#pragma unroll
    for (int nf = 0; nf < 8; nf++)
#pragma unroll
        for (int e = 0; e < 4; e++) o_acc[nf][e] = 0.f;

    for (int kb = 0; kb < 16; kb++) {
        if (kb + 1 < 16) {
            int st = (kb + 1) & 1;
            flash_load_kv(Kbase + st * KV_STAGE_HALFS, Vbase + st * KV_STAGE_HALFS,
                          Kg + (size_t)(kb + 1) * 128 * DHEAD,
                          Vg + (size_t)(kb + 1) * 128 * DHEAD, tid);
            if (tid < 32) cp16(mfbase + st * 128 + tid * 4, Mg + (kb + 1) * 128 + tid * 4);
            cp_commit();
            cp_wait<1>();
        } else {
            cp_wait<0>();
        }
        __syncthreads();

        const int st = kb & 1;
        const __half (*Ks)[HSTR] = (const __half (*)[HSTR])(Kbase + st * KV_STAGE_HALFS);
        const __half (*Vs)[HSTR] = (const __half (*)[HSTR])(Vbase + st * KV_STAGE_HALFS);
        const float* mskf = mfbase + st * 128;

#pragma unroll
        for (int half = 0; half < 2; half++) {
            const int base = half * 64;

            float s_acc[8][4];
#pragma unroll
            for (int nf = 0; nf < 8; nf++)
#pragma unroll
                for (int e = 0; e < 4; e++) s_acc[nf][e] = 0.f;
#pragma unroll
            for (int kk = 0; kk < 4; kk++) {
#pragma unroll
                for (int np = 0; np < 4; np++) {
                    unsigned b0, b1, b2, b3;
                    ldsm_x4(b0, b1, b2, b3,
                            &Ks[base + np * 16 + lrow][kk * 16 + lcol]);
                    mma_f16(s_acc[2 * np][0], s_acc[2 * np][1],
                            s_acc[2 * np][2], s_acc[2 * np][3],
                            qf[kk][0], qf[kk][1], qf[kk][2], qf[kk][3], b0, b2);
                    mma_f16(s_acc[2 * np + 1][0], s_acc[2 * np + 1][1],
                            s_acc[2 * np + 1][2], s_acc[2 * np + 1][3],
                            qf[kk][0], qf[kk][1], qf[kk][2], qf[kk][3], b1, b3);
                }
            }

            float mx[2] = {NEG_INF, NEG_INF};
#pragma unroll
            for (int nf = 0; nf < 8; nf++) {
                int c0 = base + nf * 8 + tig * 2;
                float2 mm = *(const float2*)(&mskf[c0]);
                s_acc[nf][0] += mm.x;
                s_acc[nf][1] += mm.y;
                s_acc[nf][2] += mm.x;
                s_acc[nf][3] += mm.y;
                mx[0] = fmaxf(mx[0], fmaxf(s_acc[nf][0], s_acc[nf][1]));
                mx[1] = fmaxf(mx[1], fmaxf(s_acc[nf][2], s_acc[nf][3]));
            }
#pragma unroll
            for (int off = 1; off < 4; off <<= 1) {
                mx[0] = fmaxf(mx[0], __shfl_xor_sync(0xffffffffu, mx[0], off));
                mx[1] = fmaxf(mx[1], __shfl_xor_sync(0xffffffffu, mx[1], off));
            }

            float alpha[2], mc[2];
#pragma unroll
            for (int r = 0; r < 2; r++) {
                float mnew = fmaxf(m_i[r], mx[r]);
                alpha[r] = ex2(clamp_m(m_i[r]) - clamp_m(mnew));
                m_i[r] = mnew;
                mc[r] = clamp_m(mnew);
            }

            unsigned pA[8][2];
            float ps[2] = {0.f, 0.f};
#pragma unroll
            for (int nf = 0; nf < 8; nf++) {
                float p0 = ex2(s_acc[nf][0] - mc[0]);
                float p1 = ex2(s_acc[nf][1] - mc[0]);
                float p2 = ex2(s_acc[nf][2] - mc[1]);
                float p3 = ex2(s_acc[nf][3] - mc[1]);
                ps[0] += p0 + p1;
                ps[1] += p2 + p3;
                pA[nf][0] = pack_h2(p0, p1);
                pA[nf][1] = pack_h2(p2, p3);
            }
#pragma unroll
            for (int off = 1; off < 4; off <<= 1) {
                ps[0] += __shfl_xor_sync(0xffffffffu, ps[0], off);
                ps[1] += __shfl_xor_sync(0xffffffffu, ps[1], off);
            }
            l_i[0] = l_i[0] * alpha[0] + ps[0];
            l_i[1] = l_i[1] * alpha[1] + ps[1];

#pragma unroll
            for (int nf = 0; nf < 8; nf++) {
                o_acc[nf][0] *= alpha[0];
                o_acc[nf][1] *= alpha[0];
                o_acc[nf][2] *= alpha[1];
                o_acc[nf][3] *= alpha[1];
            }

#pragma unroll
            for (int j = 0; j < 4; j++) {
                int kk = base + j * 16;
                unsigned a0 = pA[2 * j][0];
                unsigned a1 = pA[2 * j][1];
                unsigned a2 = pA[2 * j + 1][0];
                unsigned a3 = pA[2 * j + 1][1];
#pragma unroll
                for (int nfp = 0; nfp < 4; nfp++) {
                    int mt = lane >> 3, ri = lane & 7;
                    const __half* vp = &Vs[kk + ri + ((mt & 1) << 3)][nfp * 16 + ((mt >> 1) << 3)];
                    unsigned r0, r1, r2, r3;
                    ldsm_x4_trans(r0, r1, r2, r3, vp);
                    int nf = nfp * 2;
                    mma_f16(o_acc[nf][0], o_acc[nf][1], o_acc[nf][2], o_acc[nf][3],
                            a0, a1, a2, a3, r0, r1);
                    mma_f16(o_acc[nf + 1][0], o_acc[nf + 1][1], o_acc[nf + 1][2], o_acc[nf + 1][3],
                            a0, a1, a2, a3, r2, r3);
                }
            }
        }
        __syncthreads();
    }

    float inv_l[2] = {1.f / l_i[0], 1.f / l_i[1]};
#pragma unroll
    for (int nf = 0; nf < 8; nf++)
#pragma unroll
        for (int eh = 0; eh < 2; eh++) {
            int t = qb * 128 + row0 + g + eh * 8;
            int d = nf * 8 + tig * 2;
            int m = t * BATCH + b;
            unsigned pv = pack_h2(o_acc[nf][eh * 2] * inv_l[eh],
                                  o_acc[nf][eh * 2 + 1] * inv_l[eh]);
            *(unsigned*)(&g_att[(size_t)m * DMODEL + hh * DHEAD + d]) = pv;
        }
}

// ---------------------------------------------------------------------------
// Kernel 3b: LayerNorm per row (1024 elems), two-pass, register-resident.
// ---------------------------------------------------------------------------
__device__ __forceinline__ float block_sum256(float v) {
    __shared__ float red[8];
#pragma unroll
    for (int off = 16; off > 0; off >>= 1) v += __shfl_xor_sync(0xffffffffu, v, off);
    if ((threadIdx.x & 31) == 0) red[threadIdx.x >> 5] = v;
    __syncthreads();
    v = red[0] + red[1] + red[2] + red[3] + red[4] + red[5] + red[6] + red[7];
    __syncthreads();
    return v;
}

__global__ __launch_bounds__(256) void layernorm_kernel(
    const float* __restrict__ lng, const float* __restrict__ lnb,
    float* __restrict__ out)
{
    const int row = blockIdx.x;
    const int tid = threadIdx.x;
    const float* x = g_res + (size_t)row * DMODEL;
    float4 v = *(const float4*)(x + tid * 4);
    float s = block_sum256(v.x + v.y + v.z + v.w);
    float mu = s * (1.f / DMODEL);
    float dx = v.x - mu, dy = v.y - mu, dz = v.z - mu, dw = v.w - mu;
    float sq = block_sum256(dx * dx + dy * dy + dz * dz + dw * dw);
    float var = sq * (1.f / DMODEL);
    float rstd = rsqrtf(var + 1e-5f);
    float4 gg = *(const float4*)(lng + tid * 4);
    float4 bb = *(const float4*)(lnb + tid * 4);
    float4 r;
    r.x = dx * rstd * gg.x + bb.x;
    r.y = dy * rstd * gg.y + bb.y;
    r.z = dz * rstd * gg.z + bb.z;
    r.w = dw * rstd * gg.w + bb.w;
    *(float4*)(out + (size_t)row * DMODEL + tid * 4) = r;
}

// ---------------------------------------------------------------------------
extern "C" void kernel_launch(void* const* d_in, const int* in_sizes, int n_in,
                              void* d_out, int out_size) {
    const float* h = (const float*)d_in[0];
    const int* mask = (const int*)d_in[1];
    const float* wq = (const float*)d_in[2];
    const float* wkv = (const float*)d_in[3];
    const float* wo = (const float*)d_in[4];
    const float* lng = (const float*)d_in[5];
    const float* lnb = (const float*)d_in[6];
    float* out = (float*)d_out;

    cudaFuncSetAttribute(flash_attn_kernel,
                         cudaFuncAttributeMaxDynamicSharedMemorySize, FLASH_SMEM_BYTES);
    cudaFuncSetAttribute(qkv_gemm_kernel,
                         cudaFuncAttributeMaxDynamicSharedMemorySize, GEMM_SMEM_BYTES);
    cudaFuncSetAttribute(outproj_gemm_kernel,
                         cudaFuncAttributeMaxDynamicSharedMemorySize, GEMM_SMEM_BYTES);

    conv_all_kernel<<<(TOT4 + T_LEN + 255) / 256, 256>>>(h, wq, wkv, wo, mask);
    qkv_gemm_kernel<<<dim3(128, 24), 128, GEMM_SMEM_BYTES>>>();
    flash_attn_kernel<<<dim3(16, 64), 256, FLASH_SMEM_BYTES>>>();
    outproj_gemm_kernel<<<dim3(128, 8), 128, GEMM_SMEM_BYTES>>>(h);
    layernorm_kernel<<<MROWS, 256>>>(lng, lnb, out);
}

// round 12
// speedup vs baseline: 1.1636x; 1.0093x over previous
#include <cuda_runtime.h>
#include <cuda_fp16.h>
#include <cstdint>

// ---------------------------------------------------------------------------
// MultiHeadAttn: T=2048, B=4, N_HEAD=16, D_HEAD=64, D_MODEL=1024
// Round 12: projection GEMMs with fp16 accumulators + 64x64 warp tiles
// (2x smem arithmetic intensity: 21->32 FLOP/B). BM=BN=128, 128 thr, 3 CTA/SM.
// Flash (fp32 softmax path) / conv / LN unchanged from R11 best.
// ---------------------------------------------------------------------------

#define T_LEN 2048
#define BATCH 4
#define NHEAD 16
#define DHEAD 64
#define DMODEL 1024
#define MROWS (T_LEN * BATCH)        // 8192
#define QSCALE_LOG2E 0.180336878f    // (1/sqrt(64)) * log2(e)
#define MASKF -1e38f

__device__ __half g_hh[MROWS * DMODEL];
__device__ __half g_wqkvh[3072 * DMODEL];
__device__ __half g_woh[DMODEL * DMODEL];
__device__ float  g_mskf[BATCH * T_LEN];                // 0 or -1e38, [b][t]
__device__ __half g_Q[BATCH * NHEAD * T_LEN * DHEAD];   // [bh][t][d]
__device__ __half g_K[BATCH * NHEAD * T_LEN * DHEAD];
__device__ __half g_V[BATCH * NHEAD * T_LEN * DHEAD];
__device__ __half g_att[MROWS * DMODEL];
__device__ float  g_res[MROWS * DMODEL];

#define NEG_INF __int_as_float(0xff800000)

__device__ __forceinline__ float clamp_m(float x) { return fmaxf(x, -1e30f); }

__device__ __forceinline__ float ex2(float x) {
    float r;
    asm("ex2.approx.ftz.f32 %0, %1;" : "=f"(r) : "f"(x));
    return r;
}

// fp32-accum fp16 mma (flash path)
__device__ __forceinline__ void mma_f16(float& c0, float& c1, float& c2, float& c3,
                                        unsigned a0, unsigned a1, unsigned a2, unsigned a3,
                                        unsigned b0, unsigned b1) {
    asm volatile(
        "mma.sync.aligned.m16n8k16.row.col.f32.f16.f16.f32 "
        "{%0,%1,%2,%3},{%4,%5,%6,%7},{%8,%9},{%0,%1,%2,%3};"
        : "+f"(c0), "+f"(c1), "+f"(c2), "+f"(c3)
        : "r"(a0), "r"(a1), "r"(a2), "r"(a3), "r"(b0), "r"(b1));
}

// fp16-accum fp16 mma (projection GEMMs): D/C are 2 regs = 4 halves
__device__ __forceinline__ void mma_f16h(unsigned& d0, unsigned& d1,
                                         unsigned a0, unsigned a1, unsigned a2, unsigned a3,
                                         unsigned b0, unsigned b1) {
    asm volatile(
        "mma.sync.aligned.m16n8k16.row.col.f16.f16.f16.f16 "
        "{%0,%1},{%2,%3,%4,%5},{%6,%7},{%0,%1};"
        : "+r"(d0), "+r"(d1)
        : "r"(a0), "r"(a1), "r"(a2), "r"(a3), "r"(b0), "r"(b1));
}

__device__ __forceinline__ void ldsm_x4(unsigned& r0, unsigned& r1,
                                        unsigned& r2, unsigned& r3,
                                        const __half* p) {
    unsigned sa = (unsigned)__cvta_generic_to_shared(p);
    asm volatile("ldmatrix.sync.aligned.m8n8.x4.shared.b16 {%0,%1,%2,%3}, [%4];"
                 : "=r"(r0), "=r"(r1), "=r"(r2), "=r"(r3) : "r"(sa));
}

__device__ __forceinline__ void ldsm_x4_trans(unsigned& r0, unsigned& r1,
                                              unsigned& r2, unsigned& r3,
                                              const __half* p) {
    unsigned sa = (unsigned)__cvta_generic_to_shared(p);
    asm volatile("ldmatrix.sync.aligned.m8n8.x4.trans.shared.b16 {%0,%1,%2,%3}, [%4];"
                 : "=r"(r0), "=r"(r1), "=r"(r2), "=r"(r3) : "r"(sa));
}

__device__ __forceinline__ unsigned pack_h2(float a, float b) {
    __half2 h = __floats2half2_rn(a, b);
    return *(unsigned*)&h;
}

__device__ __forceinline__ void cp16(const void* smem_dst, const void* gsrc) {
    unsigned sa = (unsigned)__cvta_generic_to_shared(smem_dst);
    unsigned long long ga = (unsigned long long)__cvta_generic_to_global(gsrc);
    asm volatile("cp.async.cg.shared.global [%0], [%1], 16;" :: "r"(sa), "l"(ga));
}
__device__ __forceinline__ void cp_commit() { asm volatile("cp.async.commit_group;"); }
template <int N>
__device__ __forceinline__ void cp_wait() { asm volatile("cp.async.wait_group %0;" :: "n"(N)); }

// ---------------------------------------------------------------------------
// Kernel 0: fused dtype converts + mask->float pack
// ---------------------------------------------------------------------------
#define H4   (MROWS * DMODEL / 4)
#define WQ4  (1024 * DMODEL / 4)
#define WKV4 (2048 * DMODEL / 4)
#define WO4  (DMODEL * DMODEL / 4)
#define TOT4 (H4 + WQ4 + WKV4 + WO4)

__global__ __launch_bounds__(256) void conv_all_kernel(
    const float* __restrict__ h, const float* __restrict__ wq,
    const float* __restrict__ wkv, const float* __restrict__ wo,
    const int* __restrict__ mask)
{
    int i = blockIdx.x * 256 + threadIdx.x;
    if (i < TOT4) {
        const float* src;
        __half* dst;
        int off;
        if (i < H4) { src = h; dst = g_hh; off = i; }
        else if (i < H4 + WQ4) { src = wq; dst = g_wqkvh; off = i - H4; }
        else if (i < H4 + WQ4 + WKV4) { src = wkv; dst = g_wqkvh + 1024 * DMODEL; off = i - H4 - WQ4; }
        else { src = wo; dst = g_woh; off = i - H4 - WQ4 - WKV4; }
        float4 v = ((const float4*)src)[off];
        uint2 u = {pack_h2(v.x, v.y), pack_h2(v.z, v.w)};
        ((uint2*)dst)[off] = u;
    } else {
        int t = i - TOT4;
        if (t < T_LEN) {
#pragma unroll
            for (int b = 0; b < BATCH; b++)
                g_mskf[b * T_LEN + t] = (mask[t * BATCH + b] != 0) ? MASKF : 0.f;
        }
    }
}

// ---------------------------------------------------------------------------
// fp16-accum GEMM: BM=BN=128, BK=64; 128 threads (4 warps 2x2, warp tile
// 64x64, fp16 acc = 64 regs). 2-stage cp.async ring. 3 CTAs/SM.
// ---------------------------------------------------------------------------
#define BK 64
#define HSTR 72
#define GEMM_A_HALFS (128 * HSTR)                    // 9216
#define GEMM_STAGE_HALFS (2 * 128 * HSTR)            // 18432
#define GEMM_SMEM_BYTES (2 * GEMM_STAGE_HALFS * 2)   // 73728

__device__ __forceinline__ void gemm_load_stage(__half* stage,
                                                const __half* Ag, const __half* Bg,
                                                int tid) {
    __half* As = stage;
    __half* Bs = stage + GEMM_A_HALFS;
#pragma unroll
    for (int i = 0; i < 8; i++) {                 // A: 1024 chunks (128 rows x 8)
        int s = tid + i * 128;
        int r = s >> 3, c8 = (s & 7) << 3;
        cp16(As + r * HSTR + c8, Ag + (size_t)r * DMODEL + c8);
    }
#pragma unroll
    for (int i = 0; i < 8; i++) {                 // B: 1024 chunks
        int s = tid + i * 128;
        int r = s >> 3, c8 = (s & 7) << 3;
        cp16(Bs + r * HSTR + c8, Bg + (size_t)r * DMODEL + c8);
    }
}

// acc[mf][nf][eh] : mf 0..3 (16-row bands), nf 0..7 (8-col bands), eh 0/1
// (row g / g+8), each unsigned = half2 at cols {2tig, 2tig+1}.
__device__ __forceinline__ void gemm_mainloop(__half* smem, const __half* Ag,
                                              const __half* Bg, unsigned acc[4][8][2],
                                              int tid) {
    const int warp = tid >> 5, lane = tid & 31;
    const int wr = warp >> 1, wc = warp & 1;
    const int lrow = lane & 15, lcol = (lane >> 4) << 3;

    gemm_load_stage(smem, Ag, Bg, tid);
    cp_commit();

    for (int kt = 0; kt < 16; kt++) {
        if (kt + 1 < 16) {
            gemm_load_stage(smem + ((kt + 1) & 1) * GEMM_STAGE_HALFS,
                            Ag + (kt + 1) * BK, Bg + (kt + 1) * BK, tid);
            cp_commit();
            cp_wait<1>();
        } else {
            cp_wait<0>();
        }
        __syncthreads();

        const __half* stage = smem + (kt & 1) * GEMM_STAGE_HALFS;
        const __half (*As)[HSTR] = (const __half (*)[HSTR])stage;
        const __half (*Bs)[HSTR] = (const __half (*)[HSTR])(stage + GEMM_A_HALFS);
#pragma unroll
        for (int kk = 0; kk < BK; kk += 16) {
            unsigned a[4][4];
#pragma unroll
            for (int mf = 0; mf < 4; mf++)
                ldsm_x4(a[mf][0], a[mf][1], a[mf][2], a[mf][3],
                        &As[wr * 64 + mf * 16 + lrow][kk + lcol]);
#pragma unroll
            for (int np = 0; np < 4; np++) {
                unsigned b0, b1, b2, b3;   // b0/b2 -> nf=2np; b1/b3 -> nf=2np+1
                ldsm_x4(b0, b1, b2, b3, &Bs[wc * 64 + np * 16 + lrow][kk + lcol]);
#pragma unroll
                for (int mf = 0; mf < 4; mf++) {
                    mma_f16h(acc[mf][2 * np][0], acc[mf][2 * np][1],
                             a[mf][0], a[mf][1], a[mf][2], a[mf][3], b0, b2);
                    mma_f16h(acc[mf][2 * np + 1][0], acc[mf][2 * np + 1][1],
                             a[mf][0], a[mf][1], a[mf][2], a[mf][3], b1, b3);
                }
            }
        }
        __syncthreads();
    }
}

// Kernel 1: QKV projection. grid (64, 24): bn<8 -> Q, 8..15 -> K, 16..23 -> V
__global__ __launch_bounds__(128, 3) void qkv_gemm_kernel() {
    extern __shared__ __half smem[];
    const int bm = blockIdx.x, bn = blockIdx.y;
    const int tid = threadIdx.x;
    const int warp = tid >> 5, lane = tid & 31;
    const int wr = warp >> 1, wc = warp & 1;
    const int g = lane >> 2, tig = lane & 3;

    unsigned acc[4][8][2];
#pragma unroll
    for (int i = 0; i < 4; i++)
#pragma unroll
        for (int j = 0; j < 8; j++) { acc[i][j][0] = 0u; acc[i][j][1] = 0u; }

    gemm_mainloop(smem, g_hh + (size_t)bm * 128 * DMODEL,
                  g_wqkvh + (size_t)bn * 128 * DMODEL, acc, tid);

    const int sec = bn >> 3;
    __half* dst = (sec == 0) ? g_Q : ((sec == 1) ? g_K : g_V);
#pragma unroll
    for (int mf = 0; mf < 4; mf++)
#pragma unroll
        for (int nf = 0; nf < 8; nf++)
#pragma unroll
            for (int eh = 0; eh < 2; eh++) {
                int rl = wr * 64 + mf * 16 + g + eh * 8;
                int cl = wc * 64 + nf * 8 + tig * 2;
                int m = bm * 128 + rl;
                int t = m >> 2, b = m & 3;
                int o = (bn & 7) * 128 + cl;
                int head = o >> 6, d = o & 63;
                *(unsigned*)(&dst[(((size_t)(b * NHEAD + head) * T_LEN + t) << 6) + d]) =
                    acc[mf][nf][eh];
            }
}

// Kernel 3a: out projection + residual. grid (64, 8).
__global__ __launch_bounds__(128, 3) void outproj_gemm_kernel(const float* __restrict__ hmat) {
    extern __shared__ __half smem[];
    const int bm = blockIdx.x, bn = blockIdx.y;
    const int tid = threadIdx.x;
    const int warp = tid >> 5, lane = tid & 31;
    const int wr = warp >> 1, wc = warp & 1;
    const int g = lane >> 2, tig = lane & 3;

    unsigned acc[4][8][2];
#pragma unroll
    for (int i = 0; i < 4; i++)
#pragma unroll
        for (int j = 0; j < 8; j++) { acc[i][j][0] = 0u; acc[i][j][1] = 0u; }

    gemm_mainloop(smem, g_att + (size_t)bm * 128 * DMODEL,
                  g_woh + (size_t)bn * 128 * DMODEL, acc, tid);

#pragma unroll
    for (int mf = 0; mf < 4; mf++)
#pragma unroll
        for (int nf = 0; nf < 8; nf++)
#pragma unroll
            for (int eh = 0; eh < 2; eh++) {
                int rl = wr * 64 + mf * 16 + g + eh * 8;
                int cl = wc * 64 + nf * 8 + tig * 2;
                int m = bm * 128 + rl;
                int col = bn * 128 + cl;
                size_t idx = (size_t)m * DMODEL + col;
                __half2 hv = *(__half2*)&acc[mf][nf][eh];
                float2 rr = *(const float2*)(hmat + idx);
                float2 o;
                o.x = __low2float(hv) + rr.x;
                o.y = __high2float(hv) + rr.y;
                *(float2*)(g_res + idx) = o;
            }
}

// ---------------------------------------------------------------------------
// Kernel 2: flash attention (R6/R11 proven). 256 threads, 2 CTA/SM.
// ---------------------------------------------------------------------------
#define KV_STAGE_HALFS (128 * HSTR)
#define FLASH_Q_OFF 0
#define FLASH_K_OFF (128 * HSTR)
#define FLASH_V_OFF (FLASH_K_OFF + 2 * KV_STAGE_HALFS)
#define FLASH_MSK_OFF (FLASH_V_OFF + 2 * KV_STAGE_HALFS)   // halves
#define FLASH_SMEM_BYTES (FLASH_MSK_OFF * 2 + 2 * 128 * 4 + 256)

__device__ __forceinline__ void flash_load_kv(__half* Kdst, __half* Vdst,
                                              const __half* Kg, const __half* Vg,
                                              int tid) {
#pragma unroll
    for (int i = 0; i < 4; i++) {
        int s = tid + i * 256;
        int r = s >> 3, c8 = (s & 7) << 3;
        cp16(Kdst + r * HSTR + c8, Kg + (size_t)r * DHEAD + c8);
        cp16(Vdst + r * HSTR + c8, Vg + (size_t)r * DHEAD + c8);
    }
}

__global__ __launch_bounds__(256, 2) void flash_attn_kernel() {
    extern __shared__ __half sm[];
    __half (*Qs)[HSTR] = (__half (*)[HSTR])(sm + FLASH_Q_OFF);
    __half* Kbase = sm + FLASH_K_OFF;
    __half* Vbase = sm + FLASH_V_OFF;
    float* mfbase = (float*)(sm + FLASH_MSK_OFF);

    const int qb = blockIdx.x, bh = blockIdx.y;
    const int b = bh >> 4, hh = bh & 15;
    const int tid = threadIdx.x;
    const int warp = tid >> 5, lane = tid & 31;
    const int g = lane >> 2, tig = lane & 3;
    const int lrow = lane & 15, lcol = (lane >> 4) << 3;
    const int row0 = warp * 16;

    const __half* Qg = g_Q + (size_t)bh * T_LEN * DHEAD + (size_t)qb * 128 * DHEAD;
    const __half* Kg = g_K + (size_t)bh * T_LEN * DHEAD;
    const __half* Vg = g_V + (size_t)bh * T_LEN * DHEAD;
    const float* Mg = g_mskf + (size_t)b * T_LEN;

    flash_load_kv(Kbase, Vbase, Kg, Vg, tid);
    if (tid < 32) cp16(mfbase + tid * 4, Mg + tid * 4);
    cp_commit();

    const __half2 qs2 = __float2half2_rn(QSCALE_LOG2E);
#pragma unroll
    for (int i = 0; i < 4; i++) {
        int s = tid + i * 256;
        int r = s >> 3, c8 = (s & 7) << 3;
        uint4 u = *(const uint4*)(Qg + (size_t)r * DHEAD + c8);
        __half2* hp = (__half2*)&u;
#pragma unroll
        for (int q = 0; q < 4; q++) hp[q] = __hmul2(hp[q], qs2);
        *(uint4*)(&Qs[r][c8]) = u;
    }
    __syncthreads();

    unsigned qf[4][4];
#pragma unroll
    for (int kk = 0; kk < 4; kk++)
        ldsm_x4(qf[kk][0], qf[kk][1], qf[kk][2], qf[kk][3],
                &Qs[row0 + lrow][kk * 16 + lcol]);

    float m_i[2] = {NEG_INF, NEG_INF};
    float l_i[2] = {0.f, 0.f};
    float o_acc[8][4];
#pragma unroll
    for (int nf = 0; nf < 8; nf++)
#pragma unroll
        for (int e = 0; e < 4; e++) o_acc[nf][e] = 0.f;

    for (int kb = 0; kb < 16; kb++) {
        if (kb + 1 < 16) {
            int st = (kb + 1) & 1;
            flash_load_kv(Kbase + st * KV_STAGE_HALFS, Vbase + st * KV_STAGE_HALFS,
                          Kg + (size_t)(kb + 1) * 128 * DHEAD,
                          Vg + (size_t)(kb + 1) * 128 * DHEAD, tid);
            if (tid < 32) cp16(mfbase + st * 128 + tid * 4, Mg + (kb + 1) * 128 + tid * 4);
            cp_commit();
            cp_wait<1>();
        } else {
            cp_wait<0>();
        }
        __syncthreads();

        const int st = kb & 1;
        const __half (*Ks)[HSTR] = (const __half (*)[HSTR])(Kbase + st * KV_STAGE_HALFS);
        const __half (*Vs)[HSTR] = (const __half (*)[HSTR])(Vbase + st * KV_STAGE_HALFS);
        const float* mskf = mfbase + st * 128;

#pragma unroll
        for (int half = 0; half < 2; half++) {
            const int base = half * 64;

            float s_acc[8][4];
#pragma unroll
            for (int nf = 0; nf < 8; nf++)
#pragma unroll
                for (int e = 0; e < 4; e++) s_acc[nf][e] = 0.f;
#pragma unroll
            for (int kk = 0; kk < 4; kk++) {
#pragma unroll
                for (int np = 0; np < 4; np++) {
                    unsigned b0, b1, b2, b3;
                    ldsm_x4(b0, b1, b2, b3,
                            &Ks[base + np * 16 + lrow][kk * 16 + lcol]);
                    mma_f16(s_acc[2 * np][0], s_acc[2 * np][1],
                            s_acc[2 * np][2], s_acc[2 * np][3],
                            qf[kk][0], qf[kk][1], qf[kk][2], qf[kk][3], b0, b2);
                    mma_f16(s_acc[2 * np + 1][0], s_acc[2 * np + 1][1],
                            s_acc[2 * np + 1][2], s_acc[2 * np + 1][3],
                            qf[kk][0], qf[kk][1], qf[kk][2], qf[kk][3], b1, b3);
                }
            }

            float mx[2] = {NEG_INF, NEG_INF};
#pragma unroll
            for (int nf = 0; nf < 8; nf++) {
                int c0 = base + nf * 8 + tig * 2;
                float2 mm = *(const float2*)(&mskf[c0]);
                s_acc[nf][0] += mm.x;
                s_acc[nf][1] += mm.y;
                s_acc[nf][2] += mm.x;
                s_acc[nf][3] += mm.y;
                mx[0] = fmaxf(mx[0], fmaxf(s_acc[nf][0], s_acc[nf][1]));
                mx[1] = fmaxf(mx[1], fmaxf(s_acc[nf][2], s_acc[nf][3]));
            }
#pragma unroll
            for (int off = 1; off < 4; off <<= 1) {
                mx[0] = fmaxf(mx[0], __shfl_xor_sync(0xffffffffu, mx[0], off));
                mx[1] = fmaxf(mx[1], __shfl_xor_sync(0xffffffffu, mx[1], off));
            }

            float alpha[2], mc[2];
#pragma unroll
            for (int r = 0; r < 2; r++) {
                float mnew = fmaxf(m_i[r], mx[r]);
                alpha[r] = ex2(clamp_m(m_i[r]) - clamp_m(mnew));
                m_i[r] = mnew;
                mc[r] = clamp_m(mnew);
            }

            unsigned pA[8][2];
            float ps[2] = {0.f, 0.f};
#pragma unroll
            for (int nf = 0; nf < 8; nf++) {
                float p0 = ex2(s_acc[nf][0] - mc[0]);
                float p1 = ex2(s_acc[nf][1] - mc[0]);
                float p2 = ex2(s_acc[nf][2] - mc[1]);
                float p3 = ex2(s_acc[nf][3] - mc[1]);
                ps[0] += p0 + p1;
                ps[1] += p2 + p3;
                pA[nf][0] = pack_h2(p0, p1);
                pA[nf][1] = pack_h2(p2, p3);
            }
#pragma unroll
            for (int off = 1; off < 4; off <<= 1) {
                ps[0] += __shfl_xor_sync(0xffffffffu, ps[0], off);
                ps[1] += __shfl_xor_sync(0xffffffffu, ps[1], off);
            }
            l_i[0] = l_i[0] * alpha[0] + ps[0];
            l_i[1] = l_i[1] * alpha[1] + ps[1];

#pragma unroll
            for (int nf = 0; nf < 8; nf++) {
                o_acc[nf][0] *= alpha[0];
                o_acc[nf][1] *= alpha[0];
                o_acc[nf][2] *= alpha[1];
                o_acc[nf][3] *= alpha[1];
            }

#pragma unroll
            for (int j = 0; j < 4; j++) {
                int kk = base + j * 16;
                unsigned a0 = pA[2 * j][0];
                unsigned a1 = pA[2 * j][1];
                unsigned a2 = pA[2 * j + 1][0];
                unsigned a3 = pA[2 * j + 1][1];
#pragma unroll
                for (int nfp = 0; nfp < 4; nfp++) {
                    int mt = lane >> 3, ri = lane & 7;
                    const __half* vp = &Vs[kk + ri + ((mt & 1) << 3)][nfp * 16 + ((mt >> 1) << 3)];
                    unsigned r0, r1, r2, r3;
                    ldsm_x4_trans(r0, r1, r2, r3, vp);
                    int nf = nfp * 2;
                    mma_f16(o_acc[nf][0], o_acc[nf][1], o_acc[nf][2], o_acc[nf][3],
                            a0, a1, a2, a3, r0, r1);
                    mma_f16(o_acc[nf + 1][0], o_acc[nf + 1][1], o_acc[nf + 1][2], o_acc[nf + 1][3],
                            a0, a1, a2, a3, r2, r3);
                }
            }
        }
        __syncthreads();
    }

    float inv_l[2] = {1.f / l_i[0], 1.f / l_i[1]};
#pragma unroll
    for (int nf = 0; nf < 8; nf++)
#pragma unroll
        for (int eh = 0; eh < 2; eh++) {
            int t = qb * 128 + row0 + g + eh * 8;
            int d = nf * 8 + tig * 2;
            int m = t * BATCH + b;
            unsigned pv = pack_h2(o_acc[nf][eh * 2] * inv_l[eh],
                                  o_acc[nf][eh * 2 + 1] * inv_l[eh]);
            *(unsigned*)(&g_att[(size_t)m * DMODEL + hh * DHEAD + d]) = pv;
        }
}

// ---------------------------------------------------------------------------
// Kernel 3b: LayerNorm per row (1024 elems), two-pass, register-resident.
// ---------------------------------------------------------------------------
__device__ __forceinline__ float block_sum256(float v) {
    __shared__ float red[8];
#pragma unroll
    for (int off = 16; off > 0; off >>= 1) v += __shfl_xor_sync(0xffffffffu, v, off);
    if ((threadIdx.x & 31) == 0) red[threadIdx.x >> 5] = v;
    __syncthreads();
    v = red[0] + red[1] + red[2] + red[3] + red[4] + red[5] + red[6] + red[7];
    __syncthreads();
    return v;
}

__global__ __launch_bounds__(256) void layernorm_kernel(
    const float* __restrict__ lng, const float* __restrict__ lnb,
    float* __restrict__ out)
{
    const int row = blockIdx.x;
    const int tid = threadIdx.x;
    const float* x = g_res + (size_t)row * DMODEL;
    float4 v = *(const float4*)(x + tid * 4);
    float s = block_sum256(v.x + v.y + v.z + v.w);
    float mu = s * (1.f / DMODEL);
    float dx = v.x - mu, dy = v.y - mu, dz = v.z - mu, dw = v.w - mu;
    float sq = block_sum256(dx * dx + dy * dy + dz * dz + dw * dw);
    float var = sq * (1.f / DMODEL);
    float rstd = rsqrtf(var + 1e-5f);
    float4 gg = *(const float4*)(lng + tid * 4);
    float4 bb = *(const float4*)(lnb + tid * 4);
    float4 r;
    r.x = dx * rstd * gg.x + bb.x;
    r.y = dy * rstd * gg.y + bb.y;
    r.z = dz * rstd * gg.z + bb.z;
    r.w = dw * rstd * gg.w + bb.w;
    *(float4*)(out + (size_t)row * DMODEL + tid * 4) = r;
}

// ---------------------------------------------------------------------------
extern "C" void kernel_launch(void* const* d_in, const int* in_sizes, int n_in,
                              void* d_out, int out_size) {
    const float* h = (const float*)d_in[0];
    const int* mask = (const int*)d_in[1];
    const float* wq = (const float*)d_in[2];
    const float* wkv = (const float*)d_in[3];
    const float* wo = (const float*)d_in[4];
    const float* lng = (const float*)d_in[5];
    const float* lnb = (const float*)d_in[6];
    float* out = (float*)d_out;

    cudaFuncSetAttribute(flash_attn_kernel,
                         cudaFuncAttributeMaxDynamicSharedMemorySize, FLASH_SMEM_BYTES);
    cudaFuncSetAttribute(qkv_gemm_kernel,
                         cudaFuncAttributeMaxDynamicSharedMemorySize, GEMM_SMEM_BYTES);
    cudaFuncSetAttribute(outproj_gemm_kernel,
                         cudaFuncAttributeMaxDynamicSharedMemorySize, GEMM_SMEM_BYTES);

    conv_all_kernel<<<(TOT4 + T_LEN + 255) / 256, 256>>>(h, wq, wkv, wo, mask);
    qkv_gemm_kernel<<<dim3(64, 24), 128, GEMM_SMEM_BYTES>>>();
    flash_attn_kernel<<<dim3(16, 64), 256, FLASH_SMEM_BYTES>>>();
    outproj_gemm_kernel<<<dim3(64, 8), 128, GEMM_SMEM_BYTES>>>(h);
    layernorm_kernel<<<MROWS, 256>>>(lng, lnb, out);
}

// round 13
// speedup vs baseline: 1.1818x; 1.0157x over previous
#include <cuda_runtime.h>
#include <cuda_fp16.h>
#include <cstdint>

// ---------------------------------------------------------------------------
// MultiHeadAttn: T=2048, B=4, N_HEAD=16, D_HEAD=64, D_MODEL=1024
// Round 13: persistent work-stealing CTAs for qkv/flash/outproj (removes
// wave-quantization tails). Compute cores identical to R12 (fp16-acc GEMMs,
// fp32-softmax flash). HMMA issue-rate is the established roofline.
// ---------------------------------------------------------------------------

#define T_LEN 2048
#define BATCH 4
#define NHEAD 16
#define DHEAD 64
#define DMODEL 1024
#define MROWS (T_LEN * BATCH)        // 8192
#define QSCALE_LOG2E 0.180336878f    // (1/sqrt(64)) * log2(e)
#define MASKF -1e38f

__device__ __half g_hh[MROWS * DMODEL];
__device__ __half g_wqkvh[3072 * DMODEL];
__device__ __half g_woh[DMODEL * DMODEL];
__device__ float  g_mskf[BATCH * T_LEN];                // 0 or -1e38, [b][t]
__device__ __half g_Q[BATCH * NHEAD * T_LEN * DHEAD];   // [bh][t][d]
__device__ __half g_K[BATCH * NHEAD * T_LEN * DHEAD];
__device__ __half g_V[BATCH * NHEAD * T_LEN * DHEAD];
__device__ __half g_att[MROWS * DMODEL];
__device__ float  g_res[MROWS * DMODEL];
__device__ unsigned g_tkt[4];                           // work-steal tickets

#define NEG_INF __int_as_float(0xff800000)

#define QKV_TILES   (64 * 24)
#define FLASH_TILES (16 * 64)
#define OUTP_TILES  (64 * 8)
#define QKV_GRID    444
#define FLASH_GRID  296
#define OUTP_GRID   444

__device__ __forceinline__ float clamp_m(float x) { return fmaxf(x, -1e30f); }

__device__ __forceinline__ float ex2(float x) {
    float r;
    asm("ex2.approx.ftz.f32 %0, %1;" : "=f"(r) : "f"(x));
    return r;
}

// fp32-accum fp16 mma (flash path)
__device__ __forceinline__ void mma_f16(float& c0, float& c1, float& c2, float& c3,
                                        unsigned a0, unsigned a1, unsigned a2, unsigned a3,
                                        unsigned b0, unsigned b1) {
    asm volatile(
        "mma.sync.aligned.m16n8k16.row.col.f32.f16.f16.f32 "
        "{%0,%1,%2,%3},{%4,%5,%6,%7},{%8,%9},{%0,%1,%2,%3};"
        : "+f"(c0), "+f"(c1), "+f"(c2), "+f"(c3)
        : "r"(a0), "r"(a1), "r"(a2), "r"(a3), "r"(b0), "r"(b1));
}

// fp16-accum fp16 mma (projection GEMMs)
__device__ __forceinline__ void mma_f16h(unsigned& d0, unsigned& d1,
                                         unsigned a0, unsigned a1, unsigned a2, unsigned a3,
                                         unsigned b0, unsigned b1) {
    asm volatile(
        "mma.sync.aligned.m16n8k16.row.col.f16.f16.f16.f16 "
        "{%0,%1},{%2,%3,%4,%5},{%6,%7},{%0,%1};"
        : "+r"(d0), "+r"(d1)
        : "r"(a0), "r"(a1), "r"(a2), "r"(a3), "r"(b0), "r"(b1));
}

__device__ __forceinline__ void ldsm_x4(unsigned& r0, unsigned& r1,
                                        unsigned& r2, unsigned& r3,
                                        const __half* p) {
    unsigned sa = (unsigned)__cvta_generic_to_shared(p);
    asm volatile("ldmatrix.sync.aligned.m8n8.x4.shared.b16 {%0,%1,%2,%3}, [%4];"
                 : "=r"(r0), "=r"(r1), "=r"(r2), "=r"(r3) : "r"(sa));
}

__device__ __forceinline__ void ldsm_x4_trans(unsigned& r0, unsigned& r1,
                                              unsigned& r2, unsigned& r3,
                                              const __half* p) {
    unsigned sa = (unsigned)__cvta_generic_to_shared(p);
    asm volatile("ldmatrix.sync.aligned.m8n8.x4.trans.shared.b16 {%0,%1,%2,%3}, [%4];"
                 : "=r"(r0), "=r"(r1), "=r"(r2), "=r"(r3) : "r"(sa));
}

__device__ __forceinline__ unsigned pack_h2(float a, float b) {
    __half2 h = __floats2half2_rn(a, b);
    return *(unsigned*)&h;
}

__device__ __forceinline__ void cp16(const void* smem_dst, const void* gsrc) {
    unsigned sa = (unsigned)__cvta_generic_to_shared(smem_dst);
    unsigned long long ga = (unsigned long long)__cvta_generic_to_global(gsrc);
    asm volatile("cp.async.cg.shared.global [%0], [%1], 16;" :: "r"(sa), "l"(ga));
}
__device__ __forceinline__ void cp_commit() { asm volatile("cp.async.commit_group;"); }
template <int N>
__device__ __forceinline__ void cp_wait() { asm volatile("cp.async.wait_group %0;" :: "n"(N)); }

// ---------------------------------------------------------------------------
// Kernel -1: reset work tickets (graph-capturable, runs each replay)
// ---------------------------------------------------------------------------
__global__ void reset_tkt_kernel() {
    if (threadIdx.x < 4) g_tkt[threadIdx.x] = 0u;
}

// ---------------------------------------------------------------------------
// Kernel 0: fused dtype converts + mask->float pack
// ---------------------------------------------------------------------------
#define H4   (MROWS * DMODEL / 4)
#define WQ4  (1024 * DMODEL / 4)
#define WKV4 (2048 * DMODEL / 4)
#define WO4  (DMODEL * DMODEL / 4)
#define TOT4 (H4 + WQ4 + WKV4 + WO4)

__global__ __launch_bounds__(256) void conv_all_kernel(
    const float* __restrict__ h, const float* __restrict__ wq,
    const float* __restrict__ wkv, const float* __restrict__ wo,
    const int* __restrict__ mask)
{
    int i = blockIdx.x * 256 + threadIdx.x;
    if (i < TOT4) {
        const float* src;
        __half* dst;
        int off;
        if (i < H4) { src = h; dst = g_hh; off = i; }
        else if (i < H4 + WQ4) { src = wq; dst = g_wqkvh; off = i - H4; }
        else if (i < H4 + WQ4 + WKV4) { src = wkv; dst = g_wqkvh + 1024 * DMODEL; off = i - H4 - WQ4; }
        else { src = wo; dst = g_woh; off = i - H4 - WQ4 - WKV4; }
        float4 v = ((const float4*)src)[off];
        uint2 u = {pack_h2(v.x, v.y), pack_h2(v.z, v.w)};
        ((uint2*)dst)[off] = u;
    } else {
        int t = i - TOT4;
        if (t < T_LEN) {
#pragma unroll
            for (int b = 0; b < BATCH; b++)
                g_mskf[b * T_LEN + t] = (mask[t * BATCH + b] != 0) ? MASKF : 0.f;
        }
    }
}

// ---------------------------------------------------------------------------
// fp16-accum GEMM core: BM=BN=128, BK=64; 128 threads (4 warps 2x2, warp
// tile 64x64). 2-stage cp.async ring. 3 CTAs/SM.
// ---------------------------------------------------------------------------
#define BK 64
#define HSTR 72
#define GEMM_A_HALFS (128 * HSTR)                    // 9216
#define GEMM_STAGE_HALFS (2 * 128 * HSTR)            // 18432
#define GEMM_SMEM_BYTES (2 * GEMM_STAGE_HALFS * 2)   // 73728

__device__ __forceinline__ void gemm_load_stage(__half* stage,
                                                const __half* Ag, const __half* Bg,
                                                int tid) {
    __half* As = stage;
    __half* Bs = stage + GEMM_A_HALFS;
#pragma unroll
    for (int i = 0; i < 8; i++) {
        int s = tid + i * 128;
        int r = s >> 3, c8 = (s & 7) << 3;
        cp16(As + r * HSTR + c8, Ag + (size_t)r * DMODEL + c8);
    }
#pragma unroll
    for (int i = 0; i < 8; i++) {
        int s = tid + i * 128;
        int r = s >> 3, c8 = (s & 7) << 3;
        cp16(Bs + r * HSTR + c8, Bg + (size_t)r * DMODEL + c8);
    }
}

__device__ __forceinline__ void gemm_mainloop(__half* smem, const __half* Ag,
                                              const __half* Bg, unsigned acc[4][8][2],
                                              int tid) {
    const int warp = tid >> 5, lane = tid & 31;
    const int wr = warp >> 1, wc = warp & 1;
    const int lrow = lane & 15, lcol = (lane >> 4) << 3;

    gemm_load_stage(smem, Ag, Bg, tid);
    cp_commit();

    for (int kt = 0; kt < 16; kt++) {
        if (kt + 1 < 16) {
            gemm_load_stage(smem + ((kt + 1) & 1) * GEMM_STAGE_HALFS,
                            Ag + (kt + 1) * BK, Bg + (kt + 1) * BK, tid);
            cp_commit();
            cp_wait<1>();
        } else {
            cp_wait<0>();
        }
        __syncthreads();

        const __half* stage = smem + (kt & 1) * GEMM_STAGE_HALFS;
        const __half (*As)[HSTR] = (const __half (*)[HSTR])stage;
        const __half (*Bs)[HSTR] = (const __half (*)[HSTR])(stage + GEMM_A_HALFS);
#pragma unroll
        for (int kk = 0; kk < BK; kk += 16) {
            unsigned a[4][4];
#pragma unroll
            for (int mf = 0; mf < 4; mf++)
                ldsm_x4(a[mf][0], a[mf][1], a[mf][2], a[mf][3],
                        &As[wr * 64 + mf * 16 + lrow][kk + lcol]);
#pragma unroll
            for (int np = 0; np < 4; np++) {
                unsigned b0, b1, b2, b3;
                ldsm_x4(b0, b1, b2, b3, &Bs[wc * 64 + np * 16 + lrow][kk + lcol]);
#pragma unroll
                for (int mf = 0; mf < 4; mf++) {
                    mma_f16h(acc[mf][2 * np][0], acc[mf][2 * np][1],
                             a[mf][0], a[mf][1], a[mf][2], a[mf][3], b0, b2);
                    mma_f16h(acc[mf][2 * np + 1][0], acc[mf][2 * np + 1][1],
                             a[mf][0], a[mf][1], a[mf][2], a[mf][3], b1, b3);
                }
            }
        }
        __syncthreads();
    }
}

// Kernel 1: QKV projection, persistent. tiles: bm = t%64, bn = t/64 (24).
__global__ __launch_bounds__(128, 3) void qkv_gemm_kernel() {
    extern __shared__ __half smem[];
    __shared__ int s_tile;
    const int tid = threadIdx.x;
    const int warp = tid >> 5, lane = tid & 31;
    const int wr = warp >> 1, wc = warp & 1;
    const int g = lane >> 2, tig = lane & 3;

    for (;;) {
        __syncthreads();
        if (tid == 0) s_tile = (int)atomicAdd(&g_tkt[0], 1u);
        __syncthreads();
        const int tile = s_tile;
        if (tile >= QKV_TILES) break;
        const int bm = tile & 63, bn = tile >> 6;

        unsigned acc[4][8][2];
#pragma unroll
        for (int i = 0; i < 4; i++)
#pragma unroll
            for (int j = 0; j < 8; j++) { acc[i][j][0] = 0u; acc[i][j][1] = 0u; }

        gemm_mainloop(smem, g_hh + (size_t)bm * 128 * DMODEL,
                      g_wqkvh + (size_t)bn * 128 * DMODEL, acc, tid);

        const int sec = bn >> 3;
        __half* dst = (sec == 0) ? g_Q : ((sec == 1) ? g_K : g_V);
#pragma unroll
        for (int mf = 0; mf < 4; mf++)
#pragma unroll
            for (int nf = 0; nf < 8; nf++)
#pragma unroll
                for (int eh = 0; eh < 2; eh++) {
                    int rl = wr * 64 + mf * 16 + g + eh * 8;
                    int cl = wc * 64 + nf * 8 + tig * 2;
                    int m = bm * 128 + rl;
                    int t = m >> 2, b = m & 3;
                    int o = (bn & 7) * 128 + cl;
                    int head = o >> 6, d = o & 63;
                    *(unsigned*)(&dst[(((size_t)(b * NHEAD + head) * T_LEN + t) << 6) + d]) =
                        acc[mf][nf][eh];
                }
    }
}

// Kernel 3a: out projection + residual, persistent. bm = t%64, bn = t/64 (8).
__global__ __launch_bounds__(128, 3) void outproj_gemm_kernel(const float* __restrict__ hmat) {
    extern __shared__ __half smem[];
    __shared__ int s_tile;
    const int tid = threadIdx.x;
    const int warp = tid >> 5, lane = tid & 31;
    const int wr = warp >> 1, wc = warp & 1;
    const int g = lane >> 2, tig = lane & 3;

    for (;;) {
        __syncthreads();
        if (tid == 0) s_tile = (int)atomicAdd(&g_tkt[2], 1u);
        __syncthreads();
        const int tile = s_tile;
        if (tile >= OUTP_TILES) break;
        const int bm = tile & 63, bn = tile >> 6;

        unsigned acc[4][8][2];
#pragma unroll
        for (int i = 0; i < 4; i++)
#pragma unroll
            for (int j = 0; j < 8; j++) { acc[i][j][0] = 0u; acc[i][j][1] = 0u; }

        gemm_mainloop(smem, g_att + (size_t)bm * 128 * DMODEL,
                      g_woh + (size_t)bn * 128 * DMODEL, acc, tid);

#pragma unroll
        for (int mf = 0; mf < 4; mf++)
#pragma unroll
            for (int nf = 0; nf < 8; nf++)
#pragma unroll
                for (int eh = 0; eh < 2; eh++) {
                    int rl = wr * 64 + mf * 16 + g + eh * 8;
                    int cl = wc * 64 + nf * 8 + tig * 2;
                    int m = bm * 128 + rl;
                    int col = bn * 128 + cl;
                    size_t idx = (size_t)m * DMODEL + col;
                    __half2 hv = *(__half2*)&acc[mf][nf][eh];
                    float2 rr = *(const float2*)(hmat + idx);
                    float2 o;
                    o.x = __low2float(hv) + rr.x;
                    o.y = __high2float(hv) + rr.y;
                    *(float2*)(g_res + idx) = o;
                }
    }
}

// ---------------------------------------------------------------------------
// Kernel 2: flash attention, persistent. tiles: qb = t&15, bh = t>>4.
// 256 threads, 2 CTA/SM.
// ---------------------------------------------------------------------------
#define KV_STAGE_HALFS (128 * HSTR)
#define FLASH_Q_OFF 0
#define FLASH_K_OFF (128 * HSTR)
#define FLASH_V_OFF (FLASH_K_OFF + 2 * KV_STAGE_HALFS)
#define FLASH_MSK_OFF (FLASH_V_OFF + 2 * KV_STAGE_HALFS)   // halves
#define FLASH_SMEM_BYTES (FLASH_MSK_OFF * 2 + 2 * 128 * 4 + 256)

__device__ __forceinline__ void flash_load_kv(__half* Kdst, __half* Vdst,
                                              const __half* Kg, const __half* Vg,
                                              int tid) {
#pragma unroll
    for (int i = 0; i < 4; i++) {
        int s = tid + i * 256;
        int r = s >> 3, c8 = (s & 7) << 3;
        cp16(Kdst + r * HSTR + c8, Kg + (size_t)r * DHEAD + c8);
        cp16(Vdst + r * HSTR + c8, Vg + (size_t)r * DHEAD + c8);
    }
}

__global__ __launch_bounds__(256, 2) void flash_attn_kernel() {
    extern __shared__ __half sm[];
    __half (*Qs)[HSTR] = (__half (*)[HSTR])(sm + FLASH_Q_OFF);
    __half* Kbase = sm + FLASH_K_OFF;
    __half* Vbase = sm + FLASH_V_OFF;
    float* mfbase = (float*)(sm + FLASH_MSK_OFF);
    __shared__ int s_tile;

    const int tid = threadIdx.x;
    const int warp = tid >> 5, lane = tid & 31;
    const int g = lane >> 2, tig = lane & 3;
    const int lrow = lane & 15, lcol = (lane >> 4) << 3;
    const int row0 = warp * 16;
    const __half2 qs2 = __float2half2_rn(QSCALE_LOG2E);

    for (;;) {
        __syncthreads();
        if (tid == 0) s_tile = (int)atomicAdd(&g_tkt[1], 1u);
        __syncthreads();
        const int tile = s_tile;
        if (tile >= FLASH_TILES) break;
        const int qb = tile & 15, bh = tile >> 4;
        const int b = bh >> 4, hh = bh & 15;

        const __half* Qg = g_Q + (size_t)bh * T_LEN * DHEAD + (size_t)qb * 128 * DHEAD;
        const __half* Kg = g_K + (size_t)bh * T_LEN * DHEAD;
        const __half* Vg = g_V + (size_t)bh * T_LEN * DHEAD;
        const float* Mg = g_mskf + (size_t)b * T_LEN;

        flash_load_kv(Kbase, Vbase, Kg, Vg, tid);
        if (tid < 32) cp16(mfbase + tid * 4, Mg + tid * 4);
        cp_commit();

#pragma unroll
        for (int i = 0; i < 4; i++) {
            int s = tid + i * 256;
            int r = s >> 3, c8 = (s & 7) << 3;
            uint4 u = *(const uint4*)(Qg + (size_t)r * DHEAD + c8);
            __half2* hp = (__half2*)&u;
#pragma unroll
            for (int q = 0; q < 4; q++) hp[q] = __hmul2(hp[q], qs2);
            *(uint4*)(&Qs[r][c8]) = u;
        }
        __syncthreads();

        unsigned qf[4][4];
#pragma unroll
        for (int kk = 0; kk < 4; kk++)
            ldsm_x4(qf[kk][0], qf[kk][1], qf[kk][2], qf[kk][3],
                    &Qs[row0 + lrow][kk * 16 + lcol]);

        float m_i[2] = {NEG_INF, NEG_INF};
        float l_i[2] = {0.f, 0.f};
        float o_acc[8][4];
#pragma unroll
        for (int nf = 0; nf < 8; nf++)
#pragma unroll
            for (int e = 0; e < 4; e++) o_acc[nf][e] = 0.f;

        for (int kb = 0; kb < 16; kb++) {
            if (kb + 1 < 16) {
                int st = (kb + 1) & 1;
                flash_load_kv(Kbase + st * KV_STAGE_HALFS, Vbase + st * KV_STAGE_HALFS,
                              Kg + (size_t)(kb + 1) * 128 * DHEAD,
                              Vg + (size_t)(kb + 1) * 128 * DHEAD, tid);
                if (tid < 32) cp16(mfbase + st * 128 + tid * 4, Mg + (kb + 1) * 128 + tid * 4);
                cp_commit();
                cp_wait<1>();
            } else {
                cp_wait<0>();
            }
            __syncthreads();

            const int st = kb & 1;
            const __half (*Ks)[HSTR] = (const __half (*)[HSTR])(Kbase + st * KV_STAGE_HALFS);
            const __half (*Vs)[HSTR] = (const __half (*)[HSTR])(Vbase + st * KV_STAGE_HALFS);
            const float* mskf = mfbase + st * 128;

#pragma unroll
            for (int half = 0; half < 2; half++) {
                const int base = half * 64;

                float s_acc[8][4];
#pragma unroll
                for (int nf = 0; nf < 8; nf++)
#pragma unroll
                    for (int e = 0; e < 4; e++) s_acc[nf][e] = 0.f;
#pragma unroll
                for (int kk = 0; kk < 4; kk++) {
#pragma unroll
                    for (int np = 0; np < 4; np++) {
                        unsigned b0, b1, b2, b3;
                        ldsm_x4(b0, b1, b2, b3,
                                &Ks[base + np * 16 + lrow][kk * 16 + lcol]);
                        mma_f16(s_acc[2 * np][0], s_acc[2 * np][1],
                                s_acc[2 * np][2], s_acc[2 * np][3],
                                qf[kk][0], qf[kk][1], qf[kk][2], qf[kk][3], b0, b2);
                        mma_f16(s_acc[2 * np + 1][0], s_acc[2 * np + 1][1],
                                s_acc[2 * np + 1][2], s_acc[2 * np + 1][3],
                                qf[kk][0], qf[kk][1], qf[kk][2], qf[kk][3], b1, b3);
                    }
                }

                float mx[2] = {NEG_INF, NEG_INF};
#pragma unroll
                for (int nf = 0; nf < 8; nf++) {
                    int c0 = base + nf * 8 + tig * 2;
                    float2 mm = *(const float2*)(&mskf[c0]);
                    s_acc[nf][0] += mm.x;
                    s_acc[nf][1] += mm.y;
                    s_acc[nf][2] += mm.x;
                    s_acc[nf][3] += mm.y;
                    mx[0] = fmaxf(mx[0], fmaxf(s_acc[nf][0], s_acc[nf][1]));
                    mx[1] = fmaxf(mx[1], fmaxf(s_acc[nf][2], s_acc[nf][3]));
                }
#pragma unroll
                for (int off = 1; off < 4; off <<= 1) {
                    mx[0] = fmaxf(mx[0], __shfl_xor_sync(0xffffffffu, mx[0], off));
                    mx[1] = fmaxf(mx[1], __shfl_xor_sync(0xffffffffu, mx[1], off));
                }

                float alpha[2], mc[2];
#pragma unroll
                for (int r = 0; r < 2; r++) {
                    float mnew = fmaxf(m_i[r], mx[r]);
                    alpha[r] = ex2(clamp_m(m_i[r]) - clamp_m(mnew));
                    m_i[r] = mnew;
                    mc[r] = clamp_m(mnew);
                }

                unsigned pA[8][2];
                float ps[2] = {0.f, 0.f};
#pragma unroll
                for (int nf = 0; nf < 8; nf++) {
                    float p0 = ex2(s_acc[nf][0] - mc[0]);
                    float p1 = ex2(s_acc[nf][1] - mc[0]);
                    float p2 = ex2(s_acc[nf][2] - mc[1]);
                    float p3 = ex2(s_acc[nf][3] - mc[1]);
                    ps[0] += p0 + p1;
                    ps[1] += p2 + p3;
                    pA[nf][0] = pack_h2(p0, p1);
                    pA[nf][1] = pack_h2(p2, p3);
                }
#pragma unroll
                for (int off = 1; off < 4; off <<= 1) {
                    ps[0] += __shfl_xor_sync(0xffffffffu, ps[0], off);
                    ps[1] += __shfl_xor_sync(0xffffffffu, ps[1], off);
                }
                l_i[0] = l_i[0] * alpha[0] + ps[0];
                l_i[1] = l_i[1] * alpha[1] + ps[1];

#pragma unroll
                for (int nf = 0; nf < 8; nf++) {
                    o_acc[nf][0] *= alpha[0];
                    o_acc[nf][1] *= alpha[0];
                    o_acc[nf][2] *= alpha[1];
                    o_acc[nf][3] *= alpha[1];
                }

#pragma unroll
                for (int j = 0; j < 4; j++) {
                    int kk = base + j * 16;
                    unsigned a0 = pA[2 * j][0];
                    unsigned a1 = pA[2 * j][1];
                    unsigned a2 = pA[2 * j + 1][0];
                    unsigned a3 = pA[2 * j + 1][1];
#pragma unroll
                    for (int nfp = 0; nfp < 4; nfp++) {
                        int mt = lane >> 3, ri = lane & 7;
                        const __half* vp = &Vs[kk + ri + ((mt & 1) << 3)][nfp * 16 + ((mt >> 1) << 3)];
                        unsigned r0, r1, r2, r3;
                        ldsm_x4_trans(r0, r1, r2, r3, vp);
                        int nf = nfp * 2;
                        mma_f16(o_acc[nf][0], o_acc[nf][1], o_acc[nf][2], o_acc[nf][3],
                                a0, a1, a2, a3, r0, r1);
                        mma_f16(o_acc[nf + 1][0], o_acc[nf + 1][1], o_acc[nf + 1][2], o_acc[nf + 1][3],
                                a0, a1, a2, a3, r2, r3);
                    }
                }
            }
            __syncthreads();
        }

        float inv_l[2] = {1.f / l_i[0], 1.f / l_i[1]};
#pragma unroll
        for (int nf = 0; nf < 8; nf++)
#pragma unroll
            for (int eh = 0; eh < 2; eh++) {
                int t = qb * 128 + row0 + g + eh * 8;
                int d = nf * 8 + tig * 2;
                int m = t * BATCH + b;
                unsigned pv = pack_h2(o_acc[nf][eh * 2] * inv_l[eh],
                                      o_acc[nf][eh * 2 + 1] * inv_l[eh]);
                *(unsigned*)(&g_att[(size_t)m * DMODEL + hh * DHEAD + d]) = pv;
            }
    }
}

// ---------------------------------------------------------------------------
// Kernel 3b: LayerNorm per row (1024 elems), two-pass, register-resident.
// ---------------------------------------------------------------------------
__device__ __forceinline__ float block_sum256(float v) {
    __shared__ float red[8];
#pragma unroll
    for (int off = 16; off > 0; off >>= 1) v += __shfl_xor_sync(0xffffffffu, v, off);
    if ((threadIdx.x & 31) == 0) red[threadIdx.x >> 5] = v;
    __syncthreads();
    v = red[0] + red[1] + red[2] + red[3] + red[4] + red[5] + red[6] + red[7];
    __syncthreads();
    return v;
}

__global__ __launch_bounds__(256) void layernorm_kernel(
    const float* __restrict__ lng, const float* __restrict__ lnb,
    float* __restrict__ out)
{
    const int row = blockIdx.x;
    const int tid = threadIdx.x;
    const float* x = g_res + (size_t)row * DMODEL;
    float4 v = *(const float4*)(x + tid * 4);
    float s = block_sum256(v.x + v.y + v.z + v.w);
    float mu = s * (1.f / DMODEL);
    float dx = v.x - mu, dy = v.y - mu, dz = v.z - mu, dw = v.w - mu;
    float sq = block_sum256(dx * dx + dy * dy + dz * dz + dw * dw);
    float var = sq * (1.f / DMODEL);
    float rstd = rsqrtf(var + 1e-5f);
    float4 gg = *(const float4*)(lng + tid * 4);
    float4 bb = *(const float4*)(lnb + tid * 4);
    float4 r;
    r.x = dx * rstd * gg.x + bb.x;
    r.y = dy * rstd * gg.y + bb.y;
    r.z = dz * rstd * gg.z + bb.z;
    r.w = dw * rstd * gg.w + bb.w;
    *(float4*)(out + (size_t)row * DMODEL + tid * 4) = r;
}

// ---------------------------------------------------------------------------
extern "C" void kernel_launch(void* const* d_in, const int* in_sizes, int n_in,
                              void* d_out, int out_size) {
    const float* h = (const float*)d_in[0];
    const int* mask = (const int*)d_in[1];
    const float* wq = (const float*)d_in[2];
    const float* wkv = (const float*)d_in[3];
    const float* wo = (const float*)d_in[4];
    const float* lng = (const float*)d_in[5];
    const float* lnb = (const float*)d_in[6];
    float* out = (float*)d_out;

    cudaFuncSetAttribute(flash_attn_kernel,
                         cudaFuncAttributeMaxDynamicSharedMemorySize, FLASH_SMEM_BYTES);
    cudaFuncSetAttribute(qkv_gemm_kernel,
                         cudaFuncAttributeMaxDynamicSharedMemorySize, GEMM_SMEM_BYTES);
    cudaFuncSetAttribute(outproj_gemm_kernel,
                         cudaFuncAttributeMaxDynamicSharedMemorySize, GEMM_SMEM_BYTES);

    reset_tkt_kernel<<<1, 32>>>();
    conv_all_kernel<<<(TOT4 + T_LEN + 255) / 256, 256>>>(h, wq, wkv, wo, mask);
    qkv_gemm_kernel<<<QKV_GRID, 128, GEMM_SMEM_BYTES>>>();
    flash_attn_kernel<<<FLASH_GRID, 256, FLASH_SMEM_BYTES>>>();
    outproj_gemm_kernel<<<OUTP_GRID, 128, GEMM_SMEM_BYTES>>>(h);
    layernorm_kernel<<<MROWS, 256>>>(lng, lnb, out);
}